// round 4
// baseline (speedup 1.0000x reference)
#include <cuda_runtime.h>
#include <math.h>

// Problem constants
constexpr int B_ = 8, N_ = 2048, F_ = 128, H_ = 128, O_ = 64;
constexpr int ROWS = B_ * N_;            // 16384
constexpr float NEG_INF = -1.0e9f;

// Output layout (tuple flattened in order):
// x_proj, logits, adj_A1, eye, z, z_positive, adj_A, Wa
constexpr long long OFF_XPROJ  = 0;
constexpr long long OFF_LOGITS = OFF_XPROJ  + (long long)B_ * N_ * O_;
constexpr long long OFF_ADJ1   = OFF_LOGITS + (long long)B_ * N_ * O_;
constexpr long long OFF_EYE    = OFF_ADJ1   + (long long)N_ * N_;
constexpr long long OFF_Z      = OFF_EYE    + (long long)N_ * N_;
constexpr long long OFF_ZPOS   = OFF_Z      + 1;          // odd -> 4B aligned only
constexpr long long OFF_ADJA   = OFF_ZPOS   + (long long)N_ * N_;  // odd
constexpr long long OFF_WA     = OFF_ADJA   + (long long)N_ * N_;

// Scratch (device globals -- no allocation allowed)
__device__ float g_h  [ROWS * H_];
__device__ float g_hp [ROWS * H_];
__device__ float g_xpw[ROWS * O_];
__device__ float g_es [ROWS];
__device__ float g_ed [ROWS];
__device__ float g_mx [ROWS];
__device__ float g_rs [ROWS];

// ---- packed f32x2 helpers (SASS FFMA2) ------------------------------------
typedef unsigned long long u64t;

__device__ __forceinline__ u64t splat2(float v) {
    u64t r; asm("mov.b64 %0, {%1, %1};" : "=l"(r) : "f"(v)); return r;
}
__device__ __forceinline__ u64t fma2(u64t a, u64t b, u64t c) {
    u64t d; asm("fma.rn.f32x2 %0, %1, %2, %3;" : "=l"(d) : "l"(a), "l"(b), "l"(c));
    return d;
}
__device__ __forceinline__ void unpack2(u64t v, float& lo, float& hi) {
    asm("mov.b64 {%0, %1}, %2;" : "=f"(lo), "=f"(hi) : "l"(v));
}

// ---------------------------------------------------------------------------
// K0: elementwise outputs
// ---------------------------------------------------------------------------
__global__ void k0_misc(const float* __restrict__ adjA,
                        const float* __restrict__ zpos,
                        const float* __restrict__ Wa,
                        const float* __restrict__ z,
                        float* __restrict__ out)
{
    int i4 = blockIdx.x * blockDim.x + threadIdx.x;
    if (i4 < (N_ * N_ / 4)) {
        float4 a4  = ((const float4*)adjA)[i4];
        float4 zp4 = ((const float4*)zpos)[i4];
        int g = i4 * 4;

        float* adja_dst = out + OFF_ADJA + g;   // 4B-aligned regions
        float* zpos_dst = out + OFF_ZPOS + g;
        const float* ap = (const float*)&a4;
        const float* zp = (const float*)&zp4;
#pragma unroll
        for (int l = 0; l < 4; l++) { adja_dst[l] = ap[l]; zpos_dst[l] = zp[l]; }

        float4 s4; float* sp = (float*)&s4;
#pragma unroll
        for (int l = 0; l < 4; l++) {
            float c = fminf(fmaxf(ap[l], -3.f), 3.f);
            float s = sinhf(3.f * c);
            sp[l] = fminf(fmaxf(s, -1000.f), 1000.f);
        }
        ((float4*)(out + OFF_ADJ1))[i4] = s4;

        int row = g >> 11;
        int col = g & 2047;
        float4 e4; float* ep = (float*)&e4;
#pragma unroll
        for (int l = 0; l < 4; l++) ep[l] = (col + l == row) ? 1.f : 0.f;
        ((float4*)(out + OFF_EYE))[i4] = e4;
    }
    if (blockIdx.x == 0) {
        if (threadIdx.x < O_)  out[OFF_WA + threadIdx.x] = Wa[threadIdx.x];
        if (threadIdx.x == O_) out[OFF_Z] = z[0];
    }
}

// ---------------------------------------------------------------------------
// K1: h = x @ W^T   (64-row x 128-col tile, FFMA2 inner loop)
// thread (tx,ty): cols tx*8..tx*8+7, rows ty+16i
// ---------------------------------------------------------------------------
__global__ __launch_bounds__(256) void k1_h(const float* __restrict__ x,
                                            const float* __restrict__ W)
{
    __shared__ __align__(16) float x_s[64][36];
    __shared__ __align__(16) float w_s[32][132];
    const int m0 = blockIdx.x * 64;
    const int tid = threadIdx.x, tx = tid & 15, ty = tid >> 4;

    u64t acc[4][4];
#pragma unroll
    for (int i = 0; i < 4; i++)
#pragma unroll
        for (int t = 0; t < 4; t++) acc[i][t] = 0ull;

    for (int f0 = 0; f0 < F_; f0 += 32) {
#pragma unroll
        for (int it = 0; it < 2; it++) {           // 64x32 x tile, float4
            int idx = tid + it * 256;              // 512 float4
            int mi = idx >> 3, k4 = idx & 7;
            *(float4*)&x_s[mi][k4 * 4] =
                *(const float4*)&x[(m0 + mi) * F_ + f0 + k4 * 4];
        }
#pragma unroll
        for (int it = 0; it < 16; it++) {          // 128x32 W chunk, transposed
            int idx = tid + it * 256;
            int h = idx >> 5, k = idx & 31;
            w_s[k][h] = W[h * F_ + f0 + k];
        }
        __syncthreads();
#pragma unroll
        for (int k = 0; k < 32; k++) {
            ulonglong2 b01 = *(const ulonglong2*)&w_s[k][tx * 8];
            ulonglong2 b23 = *(const ulonglong2*)&w_s[k][tx * 8 + 4];
#pragma unroll
            for (int i = 0; i < 4; i++) {
                u64t aa = splat2(x_s[ty + 16 * i][k]);
                acc[i][0] = fma2(aa, b01.x, acc[i][0]);
                acc[i][1] = fma2(aa, b01.y, acc[i][1]);
                acc[i][2] = fma2(aa, b23.x, acc[i][2]);
                acc[i][3] = fma2(aa, b23.y, acc[i][3]);
            }
        }
        __syncthreads();
    }
#pragma unroll
    for (int i = 0; i < 4; i++) {
        int r = m0 + ty + 16 * i;
        float4 o0, o1;
        unpack2(acc[i][0], o0.x, o0.y); unpack2(acc[i][1], o0.z, o0.w);
        unpack2(acc[i][2], o1.x, o1.y); unpack2(acc[i][3], o1.z, o1.w);
        *(float4*)&g_h[r * H_ + tx * 8]     = o0;
        *(float4*)&g_h[r * H_ + tx * 8 + 4] = o1;
    }
}

// ---------------------------------------------------------------------------
// K1b: e_src / e_dst (one warp per row)
// ---------------------------------------------------------------------------
__global__ void k1b_e(const float* __restrict__ a_src,
                      const float* __restrict__ a_dst)
{
    int warp = threadIdx.x >> 5, lane = threadIdx.x & 31;
    int r = blockIdx.x * 8 + warp;
    float s1 = 0.f, s2 = 0.f;
#pragma unroll
    for (int t = 0; t < 4; t++) {
        int h = lane + 32 * t;
        float v = g_h[r * H_ + h];
        s1 += v * a_src[h];
        s2 += v * a_dst[h];
    }
#pragma unroll
    for (int off = 16; off >= 1; off >>= 1) {
        s1 += __shfl_xor_sync(0xffffffffu, s1, off);
        s2 += __shfl_xor_sync(0xffffffffu, s2, off);
    }
    if (lane == 0) { g_es[r] = s1; g_ed[r] = s2; }
}

// ---------------------------------------------------------------------------
// K2: softmax row stats. One block per m-row; mask computed ONCE into smem
// and shared across all 8 batches (warp b handles batch b).
// ---------------------------------------------------------------------------
__global__ __launch_bounds__(256) void k2_stats(const float* __restrict__ adjA)
{
    __shared__ unsigned char msk[N_];
    const int m = blockIdx.x;
    const int tid = threadIdx.x;
    const int warp = tid >> 5, lane = tid & 31;

    // mask precompute (once per block)
#pragma unroll
    for (int it = 0; it < 8; it++) {
        int n = tid + it * 256;
        float adj = adjA[(long long)m * N_ + n] + (n == m ? 1.f : 0.f);
        msk[n] = (adj <= 0.f) ? 1 : 0;
    }
    __syncthreads();

    const int b = warp;                 // 8 warps = 8 batches
    const int r = b * N_ + m;
    const float es = g_es[r];
    const float* edb = g_ed + b * N_;

    float mx = -INFINITY;
    for (int n = lane; n < N_; n += 32) {
        float t = es + edb[n];
        float lr = fmaxf(t, 0.2f * t);
        float sc = msk[n] ? NEG_INF : lr;
        mx = fmaxf(mx, sc);
    }
#pragma unroll
    for (int off = 16; off >= 1; off >>= 1)
        mx = fmaxf(mx, __shfl_xor_sync(0xffffffffu, mx, off));

    float sm = 0.f;
    for (int n = lane; n < N_; n += 32) {
        float t = es + edb[n];
        float lr = fmaxf(t, 0.2f * t);
        float sc = msk[n] ? NEG_INF : lr;
        sm += __expf(sc - mx);
    }
#pragma unroll
    for (int off = 16; off >= 1; off >>= 1)
        sm += __shfl_xor_sync(0xffffffffu, sm, off);

    if (lane == 0) { g_mx[r] = mx; g_rs[r] = 1.f / sm; }
}

// ---------------------------------------------------------------------------
// K3: h_prime = elu(attn @ h).  64-row m-tile per block, FFMA2 inner loop.
// attn weights computed on the fly (never materialized).
// ---------------------------------------------------------------------------
__global__ __launch_bounds__(256) void k3_attn(const float* __restrict__ adjA)
{
    __shared__ __align__(16) float h_s[32][132];
    __shared__ float w_s[64][33];
    __shared__ float s_mx[64], s_rs[64], s_es[64];

    const int b  = blockIdx.x >> 5;
    const int m0 = (blockIdx.x & 31) * 64;
    const int rbase = b * N_ + m0;
    const int tid = threadIdx.x, tx = tid & 15, ty = tid >> 4;

    if (tid < 64) {
        s_mx[tid] = g_mx[rbase + tid];
        s_rs[tid] = g_rs[rbase + tid];
        s_es[tid] = g_es[rbase + tid];
    }
    __syncthreads();

    u64t acc[4][4];
#pragma unroll
    for (int i = 0; i < 4; i++)
#pragma unroll
        for (int t = 0; t < 4; t++) acc[i][t] = 0ull;

    const int mi = tid >> 2;            // 0..63  (w-row this thread fills)
    const int nb = (tid & 3) * 8;       // 8 n's per thread
    const int gm = m0 + mi;
    const float* arow = adjA + (long long)gm * N_;
    const float* edb  = g_ed + b * N_;
    const float es = s_es[mi], mx = s_mx[mi], rs = s_rs[mi];

    for (int n0 = 0; n0 < N_; n0 += 32) {
        // load h tile [32 n x 128 h] via float4
#pragma unroll
        for (int it = 0; it < 4; it++) {
            int idx = tid + it * 256;           // 1024 float4
            int k = idx >> 5, c4 = idx & 31;
            *(float4*)&h_s[k][c4 * 4] =
                *(const float4*)&g_h[(b * N_ + n0 + k) * H_ + c4 * 4];
        }
        // softmax weights for this 64x32 tile
        float4 a4[2], e4[2];
        a4[0] = *(const float4*)(arow + n0 + nb);
        a4[1] = *(const float4*)(arow + n0 + nb + 4);
        e4[0] = *(const float4*)(edb  + n0 + nb);
        e4[1] = *(const float4*)(edb  + n0 + nb + 4);
        const float* ap = (const float*)a4;
        const float* ep = (const float*)e4;
#pragma unroll
        for (int jj = 0; jj < 8; jj++) {
            int n = n0 + nb + jj;
            float adj = ap[jj] + (n == gm ? 1.f : 0.f);
            float t = es + ep[jj];
            float lr = fmaxf(t, 0.2f * t);
            float sc = (adj <= 0.f) ? NEG_INF : lr;
            w_s[mi][nb + jj] = __expf(sc - mx) * rs;
        }
        __syncthreads();
#pragma unroll
        for (int k = 0; k < 32; k++) {
            ulonglong2 b01 = *(const ulonglong2*)&h_s[k][tx * 8];
            ulonglong2 b23 = *(const ulonglong2*)&h_s[k][tx * 8 + 4];
#pragma unroll
            for (int i = 0; i < 4; i++) {
                u64t aa = splat2(w_s[ty + 16 * i][k]);
                acc[i][0] = fma2(aa, b01.x, acc[i][0]);
                acc[i][1] = fma2(aa, b01.y, acc[i][1]);
                acc[i][2] = fma2(aa, b23.x, acc[i][2]);
                acc[i][3] = fma2(aa, b23.y, acc[i][3]);
            }
        }
        __syncthreads();
    }
    // elu epilogue -> g_hp
#pragma unroll
    for (int i = 0; i < 4; i++) {
        int r = rbase + ty + 16 * i;
        float v[8];
        unpack2(acc[i][0], v[0], v[1]); unpack2(acc[i][1], v[2], v[3]);
        unpack2(acc[i][2], v[4], v[5]); unpack2(acc[i][3], v[6], v[7]);
        float4 o0, o1;
        o0.x = v[0] > 0.f ? v[0] : expm1f(v[0]);
        o0.y = v[1] > 0.f ? v[1] : expm1f(v[1]);
        o0.z = v[2] > 0.f ? v[2] : expm1f(v[2]);
        o0.w = v[3] > 0.f ? v[3] : expm1f(v[3]);
        o1.x = v[4] > 0.f ? v[4] : expm1f(v[4]);
        o1.y = v[5] > 0.f ? v[5] : expm1f(v[5]);
        o1.z = v[6] > 0.f ? v[6] : expm1f(v[6]);
        o1.w = v[7] > 0.f ? v[7] : expm1f(v[7]);
        *(float4*)&g_hp[r * H_ + tx * 8]     = o0;
        *(float4*)&g_hp[r * H_ + tx * 8 + 4] = o1;
    }
}

// ---------------------------------------------------------------------------
// K4: x_proj = hp @ fc2_w^T + fc2_b ; also stash xpw = x_proj + Wa
// thread (tx,ty): cols tx*4..+3, rows ty+16i
// ---------------------------------------------------------------------------
__global__ __launch_bounds__(256) void k4_xproj(const float* __restrict__ fc2w,
                                                const float* __restrict__ fc2b,
                                                const float* __restrict__ Wa,
                                                float* __restrict__ out)
{
    __shared__ __align__(16) float a_s[64][36];
    __shared__ __align__(16) float b_s[32][68];
    const int m0 = blockIdx.x * 64;
    const int tid = threadIdx.x, tx = tid & 15, ty = tid >> 4;

    u64t acc[4][2];
#pragma unroll
    for (int i = 0; i < 4; i++) { acc[i][0] = 0ull; acc[i][1] = 0ull; }

    for (int f0 = 0; f0 < H_; f0 += 32) {
#pragma unroll
        for (int it = 0; it < 2; it++) {
            int idx = tid + it * 256;              // 512 float4
            int mi = idx >> 3, k4 = idx & 7;
            *(float4*)&a_s[mi][k4 * 4] =
                *(const float4*)&g_hp[(m0 + mi) * H_ + f0 + k4 * 4];
        }
#pragma unroll
        for (int it = 0; it < 8; it++) {
            int idx = tid + it * 256;
            int o = idx >> 5, k = idx & 31;
            b_s[k][o] = fc2w[o * H_ + f0 + k];
        }
        __syncthreads();
#pragma unroll
        for (int k = 0; k < 32; k++) {
            ulonglong2 bv = *(const ulonglong2*)&b_s[k][tx * 4];
#pragma unroll
            for (int i = 0; i < 4; i++) {
                u64t aa = splat2(a_s[ty + 16 * i][k]);
                acc[i][0] = fma2(aa, bv.x, acc[i][0]);
                acc[i][1] = fma2(aa, bv.y, acc[i][1]);
            }
        }
        __syncthreads();
    }
#pragma unroll
    for (int i = 0; i < 4; i++) {
        int r = m0 + ty + 16 * i;
        int c = tx * 4;
        float v[4];
        unpack2(acc[i][0], v[0], v[1]); unpack2(acc[i][1], v[2], v[3]);
        float4 xp, xw;
        xp.x = v[0] + fc2b[c];     xp.y = v[1] + fc2b[c + 1];
        xp.z = v[2] + fc2b[c + 2]; xp.w = v[3] + fc2b[c + 3];
        xw.x = xp.x + Wa[c];       xw.y = xp.y + Wa[c + 1];
        xw.z = xp.z + Wa[c + 2];   xw.w = xp.w + Wa[c + 3];
        *(float4*)&out[OFF_XPROJ + (long long)r * O_ + c] = xp;
        *(float4*)&g_xpw[r * O_ + c] = xw;
    }
}

// ---------------------------------------------------------------------------
// K5: logits[b,m,o] = x_proj[b,m,o] - sum_n adj_A1[n,m] * xpw[b,n,o]
// ---------------------------------------------------------------------------
__global__ __launch_bounds__(256) void k5_logits(float* __restrict__ out)
{
    __shared__ __align__(16) float a_s[32][68];   // A1^T tile: a_s[k][m]
    __shared__ __align__(16) float b_s[32][68];   // xpw tile:  b_s[k][o]
    const int b  = blockIdx.x >> 5;
    const int m0 = (blockIdx.x & 31) * 64;
    const int tid = threadIdx.x, tx = tid & 15, ty = tid >> 4;
    const float* A1 = out + OFF_ADJ1;

    u64t acc[4][2];
#pragma unroll
    for (int i = 0; i < 4; i++) { acc[i][0] = 0ull; acc[i][1] = 0ull; }

    for (int n0 = 0; n0 < N_; n0 += 32) {
#pragma unroll
        for (int it = 0; it < 8; it++) {       // A1^T tile (coalesced in m)
            int idx = tid + it * 256;
            int k = idx >> 6, m = idx & 63;
            a_s[k][m] = A1[(long long)(n0 + k) * N_ + m0 + m];
        }
#pragma unroll
        for (int it = 0; it < 2; it++) {       // xpw tile, float4
            int idx = tid + it * 256;          // 512 float4
            int kk = idx >> 4, o4 = idx & 15;
            *(float4*)&b_s[kk][o4 * 4] =
                *(const float4*)&g_xpw[(b * N_ + n0 + kk) * O_ + o4 * 4];
        }
        __syncthreads();
#pragma unroll
        for (int k = 0; k < 32; k++) {
            ulonglong2 bv = *(const ulonglong2*)&b_s[k][tx * 4];
#pragma unroll
            for (int i = 0; i < 4; i++) {
                u64t aa = splat2(a_s[k][ty + 16 * i]);
                acc[i][0] = fma2(aa, bv.x, acc[i][0]);
                acc[i][1] = fma2(aa, bv.y, acc[i][1]);
            }
        }
        __syncthreads();
    }
#pragma unroll
    for (int i = 0; i < 4; i++) {
        int r = b * N_ + m0 + ty + 16 * i;
        int c = tx * 4;
        float v[4];
        unpack2(acc[i][0], v[0], v[1]); unpack2(acc[i][1], v[2], v[3]);
        float4 xp = *(const float4*)&out[OFF_XPROJ + (long long)r * O_ + c];
        float4 o;
        o.x = xp.x - v[0]; o.y = xp.y - v[1];
        o.z = xp.z - v[2]; o.w = xp.w - v[3];
        *(float4*)&out[OFF_LOGITS + (long long)r * O_ + c] = o;
    }
}

// ---------------------------------------------------------------------------
extern "C" void kernel_launch(void* const* d_in, const int* in_sizes, int n_in,
                              void* d_out, int out_size)
{
    const float* x     = (const float*)d_in[0];
    const float* adjA  = (const float*)d_in[1];
    const float* W     = (const float*)d_in[2];
    const float* a_src = (const float*)d_in[3];
    const float* a_dst = (const float*)d_in[4];
    const float* fc2w  = (const float*)d_in[5];
    const float* fc2b  = (const float*)d_in[6];
    const float* Wa    = (const float*)d_in[7];
    const float* z     = (const float*)d_in[8];
    const float* zpos  = (const float*)d_in[9];
    float* out = (float*)d_out;

    k0_misc  <<<(N_ * N_ / 4 + 255) / 256, 256>>>(adjA, zpos, Wa, z, out);
    k1_h     <<<ROWS / 64, 256>>>(x, W);
    k1b_e    <<<ROWS / 8, 256>>>(a_src, a_dst);
    k2_stats <<<N_, 256>>>(adjA);
    k3_attn  <<<B_ * (N_ / 64), 256>>>(adjA);
    k4_xproj <<<ROWS / 64, 256>>>(fc2w, fc2b, Wa, out);
    k5_logits<<<B_ * (N_ / 64), 256>>>(out);
}

// round 7
// speedup vs baseline: 1.8897x; 1.8897x over previous
#include <cuda_runtime.h>
#include <math.h>

// Problem constants
constexpr int B_ = 8, N_ = 2048, F_ = 128, H_ = 128, O_ = 64;
constexpr int ROWS = B_ * N_;            // 16384
constexpr float NEG_INF = -1.0e9f;

// Output layout (tuple flattened in order)
constexpr long long OFF_XPROJ  = 0;
constexpr long long OFF_LOGITS = OFF_XPROJ  + (long long)B_ * N_ * O_;
constexpr long long OFF_ADJ1   = OFF_LOGITS + (long long)B_ * N_ * O_;
constexpr long long OFF_EYE    = OFF_ADJ1   + (long long)N_ * N_;
constexpr long long OFF_Z      = OFF_EYE    + (long long)N_ * N_;
constexpr long long OFF_ZPOS   = OFF_Z      + 1;                    // odd -> 4B only
constexpr long long OFF_ADJA   = OFF_ZPOS   + (long long)N_ * N_;   // odd
constexpr long long OFF_WA     = OFF_ADJA   + (long long)N_ * N_;

// Scratch (device globals)
__device__ float g_h   [ROWS * H_];      // h  (row-major, for k1b)
__device__ float g_hT  [H_ * ROWS];      // h^T (B-operand for k3)
__device__ float g_hp  [ROWS * H_];      // elu(attn@h)
__device__ float g_A1T [N_ * N_];        // adj_A1 transposed (A-operand for k5)
__device__ float g_xpwT[O_ * ROWS];      // (x_proj+Wa)^T (B-operand for k5)
__device__ float g_es  [ROWS];
__device__ float g_ed  [ROWS];
__device__ float g_mx  [ROWS];
__device__ float g_rs  [ROWS];

// ---- tf32 mma helpers -----------------------------------------------------
__device__ __forceinline__ unsigned f2tf(float f) {
    unsigned u; asm("cvt.rna.tf32.f32 %0, %1;" : "=r"(u) : "f"(f)); return u;
}
__device__ __forceinline__ void mma8(float* d, const unsigned* a, const unsigned* b) {
    asm volatile("mma.sync.aligned.m16n8k8.row.col.f32.tf32.tf32.f32 "
        "{%0,%1,%2,%3},{%4,%5,%6,%7},{%8,%9},{%0,%1,%2,%3};"
        : "+f"(d[0]), "+f"(d[1]), "+f"(d[2]), "+f"(d[3])
        : "r"(a[0]), "r"(a[1]), "r"(a[2]), "r"(a[3]), "r"(b[0]), "r"(b[1]));
}

// ---------------------------------------------------------------------------
// K0: elementwise outputs (adj_A1, eye, copies)
// ---------------------------------------------------------------------------
__global__ void k0_misc(const float* __restrict__ adjA,
                        const float* __restrict__ zpos,
                        const float* __restrict__ Wa,
                        const float* __restrict__ z,
                        float* __restrict__ out)
{
    int i4 = blockIdx.x * blockDim.x + threadIdx.x;
    if (i4 < (N_ * N_ / 4)) {
        float4 a4  = ((const float4*)adjA)[i4];
        float4 zp4 = ((const float4*)zpos)[i4];
        int g = i4 * 4;
        float* adja_dst = out + OFF_ADJA + g;
        float* zpos_dst = out + OFF_ZPOS + g;
        const float* ap = (const float*)&a4;
        const float* zp = (const float*)&zp4;
#pragma unroll
        for (int l = 0; l < 4; l++) { adja_dst[l] = ap[l]; zpos_dst[l] = zp[l]; }

        float4 s4; float* sp = (float*)&s4;
#pragma unroll
        for (int l = 0; l < 4; l++) {
            float c = fminf(fmaxf(ap[l], -3.f), 3.f);
            float s = sinhf(3.f * c);
            sp[l] = fminf(fmaxf(s, -1000.f), 1000.f);
        }
        ((float4*)(out + OFF_ADJ1))[i4] = s4;

        int row = g >> 11, col = g & 2047;
        float4 e4; float* ep = (float*)&e4;
#pragma unroll
        for (int l = 0; l < 4; l++) ep[l] = (col + l == row) ? 1.f : 0.f;
        ((float4*)(out + OFF_EYE))[i4] = e4;
    }
    if (blockIdx.x == 0) {
        if (threadIdx.x < O_)  out[OFF_WA + threadIdx.x] = Wa[threadIdx.x];
        if (threadIdx.x == O_) out[OFF_Z] = z[0];
    }
}

// ---------------------------------------------------------------------------
// K0b: g_A1T = adj_A1^T  (32x32 smem tiles)
// ---------------------------------------------------------------------------
__global__ __launch_bounds__(256) void k0b_transpose(const float* __restrict__ out)
{
    __shared__ float t[32][33];
    const float* A1 = out + OFF_ADJ1;
    int bx = blockIdx.x;
    int c0 = (bx & 63) * 32;     // m tile (A1 col)
    int r0 = (bx >> 6) * 32;     // n tile (A1 row)
    int tid = threadIdx.x;
    int lr = tid >> 5, lc = tid & 31;
#pragma unroll
    for (int it = 0; it < 4; it++) {
        int row = lr + it * 8;
        t[row][lc] = A1[(long long)(r0 + row) * N_ + c0 + lc];
    }
    __syncthreads();
#pragma unroll
    for (int it = 0; it < 4; it++) {
        int row = lr + it * 8;
        g_A1T[(long long)(c0 + row) * N_ + r0 + lc] = t[lc][row];
    }
}

// ---------------------------------------------------------------------------
// K1: h = x @ W^T  (scalar FFMA, R2 form) ; also writes g_hT
// ---------------------------------------------------------------------------
__global__ __launch_bounds__(256) void k1_h(const float* __restrict__ x,
                                            const float* __restrict__ W)
{
    __shared__ float x_s[64][33];
    __shared__ float w_s[32][129];
    const int m0 = blockIdx.x * 64;
    const int tid = threadIdx.x, tx = tid & 15, ty = tid >> 4;

    float acc[4][8];
#pragma unroll
    for (int i = 0; i < 4; i++)
#pragma unroll
        for (int j = 0; j < 8; j++) acc[i][j] = 0.f;

    for (int f0 = 0; f0 < F_; f0 += 32) {
#pragma unroll
        for (int it = 0; it < 8; it++) {
            int idx = tid + it * 256;
            int mi = idx >> 5, k = idx & 31;
            x_s[mi][k] = x[(m0 + mi) * F_ + f0 + k];
        }
#pragma unroll
        for (int it = 0; it < 16; it++) {
            int idx = tid + it * 256;
            int h = idx >> 5, k = idx & 31;
            w_s[k][h] = W[h * F_ + f0 + k];
        }
        __syncthreads();
#pragma unroll
        for (int k = 0; k < 32; k++) {
            float a[4], b[8];
#pragma unroll
            for (int i = 0; i < 4; i++) a[i] = x_s[ty + 16 * i][k];
#pragma unroll
            for (int j = 0; j < 8; j++) b[j] = w_s[k][tx + 16 * j];
#pragma unroll
            for (int i = 0; i < 4; i++)
#pragma unroll
                for (int j = 0; j < 8; j++) acc[i][j] += a[i] * b[j];
        }
        __syncthreads();
    }
#pragma unroll
    for (int i = 0; i < 4; i++) {
        int r = m0 + ty + 16 * i;
#pragma unroll
        for (int j = 0; j < 8; j++) {
            int c = tx + 16 * j;
            g_h [r * H_ + c] = acc[i][j];
            g_hT[(long long)c * ROWS + r] = acc[i][j];
        }
    }
}

// ---------------------------------------------------------------------------
// K1b: e_src / e_dst (one warp per row)
// ---------------------------------------------------------------------------
__global__ void k1b_e(const float* __restrict__ a_src,
                      const float* __restrict__ a_dst)
{
    int warp = threadIdx.x >> 5, lane = threadIdx.x & 31;
    int r = blockIdx.x * 8 + warp;
    float s1 = 0.f, s2 = 0.f;
#pragma unroll
    for (int t = 0; t < 4; t++) {
        int h = lane + 32 * t;
        float v = g_h[r * H_ + h];
        s1 += v * a_src[h];
        s2 += v * a_dst[h];
    }
#pragma unroll
    for (int off = 16; off >= 1; off >>= 1) {
        s1 += __shfl_xor_sync(0xffffffffu, s1, off);
        s2 += __shfl_xor_sync(0xffffffffu, s2, off);
    }
    if (lane == 0) { g_es[r] = s1; g_ed[r] = s2; }
}

// ---------------------------------------------------------------------------
// K2: softmax row stats (mask shared across batches)
// ---------------------------------------------------------------------------
__global__ __launch_bounds__(256) void k2_stats(const float* __restrict__ adjA)
{
    __shared__ unsigned char msk[N_];
    const int m = blockIdx.x;
    const int tid = threadIdx.x;
    const int warp = tid >> 5, lane = tid & 31;
#pragma unroll
    for (int it = 0; it < 8; it++) {
        int n = tid + it * 256;
        float adj = adjA[(long long)m * N_ + n] + (n == m ? 1.f : 0.f);
        msk[n] = (adj <= 0.f) ? 1 : 0;
    }
    __syncthreads();

    const int b = warp;
    const int r = b * N_ + m;
    const float es = g_es[r];
    const float* edb = g_ed + b * N_;

    float mx = -INFINITY;
    for (int n = lane; n < N_; n += 32) {
        float t = es + edb[n];
        float lr = fmaxf(t, 0.2f * t);
        float sc = msk[n] ? NEG_INF : lr;
        mx = fmaxf(mx, sc);
    }
#pragma unroll
    for (int off = 16; off >= 1; off >>= 1)
        mx = fmaxf(mx, __shfl_xor_sync(0xffffffffu, mx, off));

    float sm = 0.f;
    for (int n = lane; n < N_; n += 32) {
        float t = es + edb[n];
        float lr = fmaxf(t, 0.2f * t);
        float sc = msk[n] ? NEG_INF : lr;
        sm += __expf(sc - mx);
    }
#pragma unroll
    for (int off = 16; off >= 1; off >>= 1)
        sm += __shfl_xor_sync(0xffffffffu, sm, off);

    if (lane == 0) { g_mx[r] = mx; g_rs[r] = 1.f / sm; }
}

// ---------------------------------------------------------------------------
// K3: h_prime = elu(attn @ h) -- tf32 mma.sync.m16n8k8
// block: 64m x 128h tile; 8 warps = 2m x 4h; warp 32m x 32h
// A = attn weights [m][k] (computed on the fly), B^T = g_hT [h][k]
// ---------------------------------------------------------------------------
__global__ __launch_bounds__(256) void k3_attn(const float* __restrict__ adjA)
{
    __shared__ unsigned w_s[64][36];     // A tile, tf32 bits
    __shared__ unsigned sB [128][36];    // B^T tile (h cols x k), tf32 bits
    __shared__ float s_mx[64], s_rs[64], s_es[64];

    const int b  = blockIdx.x >> 5;
    const int m0 = (blockIdx.x & 31) * 64;
    const int rbase = b * N_ + m0;
    const int tid = threadIdx.x;
    const int w = tid >> 5, lane = tid & 31;
    const int g = lane >> 2, tg = lane & 3;
    const int mbase = (w >> 2) * 32;     // 0 or 32
    const int hbase = (w & 3) * 32;      // 0,32,64,96

    if (tid < 64) {
        s_mx[tid] = g_mx[rbase + tid];
        s_rs[tid] = g_rs[rbase + tid];
        s_es[tid] = g_es[rbase + tid];
    }
    __syncthreads();

    float acc[2][4][4];
#pragma unroll
    for (int mf = 0; mf < 2; mf++)
#pragma unroll
        for (int nf = 0; nf < 4; nf++)
#pragma unroll
            for (int t = 0; t < 4; t++) acc[mf][nf][t] = 0.f;

    // w generation mapping (as before)
    const int mi = tid >> 2;
    const int nb = (tid & 3) * 8;
    const int gm = m0 + mi;
    const float* arow = adjA + (long long)gm * N_;
    const float* edb  = g_ed + b * N_;
    const float es = s_es[mi], mxv = s_mx[mi], rs = s_rs[mi];

    for (int n0 = 0; n0 < N_; n0 += 32) {
        // B^T tile: sB[c][kk] = tf32(g_hT[c][bN + n0 + kk])
#pragma unroll
        for (int it = 0; it < 4; it++) {
            int idx = tid + it * 256;            // 1024 float4
            int c = idx >> 3, kk4 = idx & 7;
            float4 v = *(const float4*)&g_hT[(long long)c * ROWS + b * N_ + n0 + kk4 * 4];
            uint4 u = { f2tf(v.x), f2tf(v.y), f2tf(v.z), f2tf(v.w) };
            *(uint4*)&sB[c][kk4 * 4] = u;
        }
        // attn weights for this 64x32 tile
        {
            float4 a4[2], e4[2];
            a4[0] = *(const float4*)(arow + n0 + nb);
            a4[1] = *(const float4*)(arow + n0 + nb + 4);
            e4[0] = *(const float4*)(edb  + n0 + nb);
            e4[1] = *(const float4*)(edb  + n0 + nb + 4);
            const float* ap = (const float*)a4;
            const float* ep = (const float*)e4;
#pragma unroll
            for (int jj = 0; jj < 8; jj++) {
                int n = n0 + nb + jj;
                float adj = ap[jj] + (n == gm ? 1.f : 0.f);
                float t = es + ep[jj];
                float lr = fmaxf(t, 0.2f * t);
                float sc = (adj <= 0.f) ? NEG_INF : lr;
                w_s[mi][nb + jj] = f2tf(__expf(sc - mxv) * rs);
            }
        }
        __syncthreads();

#pragma unroll
        for (int ks = 0; ks < 4; ks++) {
            int kb = ks * 8;
            unsigned afr[2][4], bfr[4][2];
#pragma unroll
            for (int mf = 0; mf < 2; mf++) {
                int mr = mbase + mf * 16 + g;
                afr[mf][0] = w_s[mr    ][kb + tg];
                afr[mf][1] = w_s[mr + 8][kb + tg];
                afr[mf][2] = w_s[mr    ][kb + 4 + tg];
                afr[mf][3] = w_s[mr + 8][kb + 4 + tg];
            }
#pragma unroll
            for (int nf = 0; nf < 4; nf++) {
                int cc = hbase + nf * 8 + g;
                bfr[nf][0] = sB[cc][kb + tg];
                bfr[nf][1] = sB[cc][kb + 4 + tg];
            }
#pragma unroll
            for (int mf = 0; mf < 2; mf++)
#pragma unroll
                for (int nf = 0; nf < 4; nf++)
                    mma8(acc[mf][nf], afr[mf], bfr[nf]);
        }
        __syncthreads();
    }

    // elu epilogue -> g_hp (float2 stores; d0,d1 and d2,d3 are col pairs)
#pragma unroll
    for (int mf = 0; mf < 2; mf++) {
#pragma unroll
        for (int nf = 0; nf < 4; nf++) {
            int c = hbase + nf * 8 + 2 * tg;
            int r0 = rbase + mbase + mf * 16 + g;
            int r1 = r0 + 8;
            float2 lo, hi;
            float v0 = acc[mf][nf][0], v1 = acc[mf][nf][1];
            float v2 = acc[mf][nf][2], v3 = acc[mf][nf][3];
            lo.x = v0 > 0.f ? v0 : expm1f(v0);
            lo.y = v1 > 0.f ? v1 : expm1f(v1);
            hi.x = v2 > 0.f ? v2 : expm1f(v2);
            hi.y = v3 > 0.f ? v3 : expm1f(v3);
            *(float2*)&g_hp[r0 * H_ + c] = lo;
            *(float2*)&g_hp[r1 * H_ + c] = hi;
        }
    }
}

// ---------------------------------------------------------------------------
// K4: x_proj = hp @ fc2_w^T + fc2_b (scalar) ; writes g_xpwT (transposed)
// ---------------------------------------------------------------------------
__global__ __launch_bounds__(256) void k4_xproj(const float* __restrict__ fc2w,
                                                const float* __restrict__ fc2b,
                                                const float* __restrict__ Wa,
                                                float* __restrict__ out)
{
    __shared__ float a_s[64][33];
    __shared__ float b_s[32][65];
    const int m0 = blockIdx.x * 64;
    const int tid = threadIdx.x, tx = tid & 15, ty = tid >> 4;

    float acc[4][4];
#pragma unroll
    for (int i = 0; i < 4; i++)
#pragma unroll
        for (int j = 0; j < 4; j++) acc[i][j] = 0.f;

    for (int f0 = 0; f0 < H_; f0 += 32) {
#pragma unroll
        for (int it = 0; it < 8; it++) {
            int idx = tid + it * 256;
            int mi = idx >> 5, k = idx & 31;
            a_s[mi][k] = g_hp[(m0 + mi) * H_ + f0 + k];
        }
#pragma unroll
        for (int it = 0; it < 8; it++) {
            int idx = tid + it * 256;
            int o = idx >> 5, k = idx & 31;
            b_s[k][o] = fc2w[o * H_ + f0 + k];
        }
        __syncthreads();
#pragma unroll
        for (int k = 0; k < 32; k++) {
            float a[4], bb[4];
#pragma unroll
            for (int i = 0; i < 4; i++) a[i] = a_s[ty + 16 * i][k];
#pragma unroll
            for (int j = 0; j < 4; j++) bb[j] = b_s[k][tx + 16 * j];
#pragma unroll
            for (int i = 0; i < 4; i++)
#pragma unroll
                for (int j = 0; j < 4; j++) acc[i][j] += a[i] * bb[j];
        }
        __syncthreads();
    }
#pragma unroll
    for (int i = 0; i < 4; i++) {
        int r = m0 + ty + 16 * i;
#pragma unroll
        for (int j = 0; j < 4; j++) {
            int c = tx + 16 * j;
            float v = acc[i][j] + fc2b[c];
            out[OFF_XPROJ + (long long)r * O_ + c] = v;
            g_xpwT[(long long)c * ROWS + r] = v + Wa[c];
        }
    }
}

// ---------------------------------------------------------------------------
// K5: logits = x_proj - A1^T @ xpw -- tf32 mma
// block: 128m x 64o; 8 warps = 4m x 2o; warp 32m x 32o
// A = g_A1T [m][k], B^T = g_xpwT [o][k]
// ---------------------------------------------------------------------------
__global__ __launch_bounds__(256) void k5_logits(float* __restrict__ out)
{
    __shared__ unsigned sA[128][36];
    __shared__ unsigned sB[64][36];
    const int b  = blockIdx.x >> 4;
    const int m0 = (blockIdx.x & 15) * 128;
    const int tid = threadIdx.x;
    const int w = tid >> 5, lane = tid & 31;
    const int g = lane >> 2, tg = lane & 3;
    const int mbase = (w >> 1) * 32;
    const int obase = (w & 1) * 32;

    float acc[2][4][4];
#pragma unroll
    for (int mf = 0; mf < 2; mf++)
#pragma unroll
        for (int nf = 0; nf < 4; nf++)
#pragma unroll
            for (int t = 0; t < 4; t++) acc[mf][nf][t] = 0.f;

    for (int n0 = 0; n0 < N_; n0 += 32) {
#pragma unroll
        for (int it = 0; it < 4; it++) {            // sA: 128x32
            int idx = tid + it * 256;
            int m = idx >> 3, kk4 = idx & 7;
            float4 v = *(const float4*)&g_A1T[(long long)(m0 + m) * N_ + n0 + kk4 * 4];
            uint4 u = { f2tf(v.x), f2tf(v.y), f2tf(v.z), f2tf(v.w) };
            *(uint4*)&sA[m][kk4 * 4] = u;
        }
#pragma unroll
        for (int it = 0; it < 2; it++) {            // sB: 64x32
            int idx = tid + it * 256;
            int o = idx >> 3, kk4 = idx & 7;
            float4 v = *(const float4*)&g_xpwT[(long long)o * ROWS + b * N_ + n0 + kk4 * 4];
            uint4 u = { f2tf(v.x), f2tf(v.y), f2tf(v.z), f2tf(v.w) };
            *(uint4*)&sB[o][kk4 * 4] = u;
        }
        __syncthreads();

#pragma unroll
        for (int ks = 0; ks < 4; ks++) {
            int kb = ks * 8;
            unsigned afr[2][4], bfr[4][2];
#pragma unroll
            for (int mf = 0; mf < 2; mf++) {
                int mr = mbase + mf * 16 + g;
                afr[mf][0] = sA[mr    ][kb + tg];
                afr[mf][1] = sA[mr + 8][kb + tg];
                afr[mf][2] = sA[mr    ][kb + 4 + tg];
                afr[mf][3] = sA[mr + 8][kb + 4 + tg];
            }
#pragma unroll
            for (int nf = 0; nf < 4; nf++) {
                int oc = obase + nf * 8 + g;
                bfr[nf][0] = sB[oc][kb + tg];
                bfr[nf][1] = sB[oc][kb + 4 + tg];
            }
#pragma unroll
            for (int mf = 0; mf < 2; mf++)
#pragma unroll
                for (int nf = 0; nf < 4; nf++)
                    mma8(acc[mf][nf], afr[mf], bfr[nf]);
        }
        __syncthreads();
    }

    // epilogue: logits = x_proj - acc
#pragma unroll
    for (int mf = 0; mf < 2; mf++) {
#pragma unroll
        for (int nf = 0; nf < 4; nf++) {
            int c = obase + nf * 8 + 2 * tg;
            int r0 = b * N_ + m0 + mbase + mf * 16 + g;
            int r1 = r0 + 8;
            float2 xp0 = *(const float2*)&out[OFF_XPROJ + (long long)r0 * O_ + c];
            float2 xp1 = *(const float2*)&out[OFF_XPROJ + (long long)r1 * O_ + c];
            float2 o0, o1;
            o0.x = xp0.x - acc[mf][nf][0]; o0.y = xp0.y - acc[mf][nf][1];
            o1.x = xp1.x - acc[mf][nf][2]; o1.y = xp1.y - acc[mf][nf][3];
            *(float2*)&out[OFF_LOGITS + (long long)r0 * O_ + c] = o0;
            *(float2*)&out[OFF_LOGITS + (long long)r1 * O_ + c] = o1;
        }
    }
}

// ---------------------------------------------------------------------------
extern "C" void kernel_launch(void* const* d_in, const int* in_sizes, int n_in,
                              void* d_out, int out_size)
{
    const float* x     = (const float*)d_in[0];
    const float* adjA  = (const float*)d_in[1];
    const float* W     = (const float*)d_in[2];
    const float* a_src = (const float*)d_in[3];
    const float* a_dst = (const float*)d_in[4];
    const float* fc2w  = (const float*)d_in[5];
    const float* fc2b  = (const float*)d_in[6];
    const float* Wa    = (const float*)d_in[7];
    const float* z     = (const float*)d_in[8];
    const float* zpos  = (const float*)d_in[9];
    float* out = (float*)d_out;

    k0_misc      <<<(N_ * N_ / 4 + 255) / 256, 256>>>(adjA, zpos, Wa, z, out);
    k0b_transpose<<<64 * 64, 256>>>(out);
    k1_h         <<<ROWS / 64, 256>>>(x, W);
    k1b_e        <<<ROWS / 8, 256>>>(a_src, a_dst);
    k2_stats     <<<N_, 256>>>(adjA);
    k3_attn      <<<B_ * (N_ / 64), 256>>>(adjA);
    k4_xproj     <<<ROWS / 64, 256>>>(fc2w, fc2b, Wa, out);
    k5_logits    <<<B_ * (N_ / 128), 256>>>(out);
}

// round 9
// speedup vs baseline: 2.0966x; 1.1095x over previous
#include <cuda_runtime.h>
#include <math.h>

// Problem constants
constexpr int B_ = 8, N_ = 2048, F_ = 128, H_ = 128, O_ = 64;
constexpr int ROWS = B_ * N_;            // 16384
constexpr float NEG_INF = -1.0e9f;

// Output layout (tuple flattened in order)
constexpr long long OFF_XPROJ  = 0;
constexpr long long OFF_LOGITS = OFF_XPROJ  + (long long)B_ * N_ * O_;
constexpr long long OFF_ADJ1   = OFF_LOGITS + (long long)B_ * N_ * O_;
constexpr long long OFF_EYE    = OFF_ADJ1   + (long long)N_ * N_;
constexpr long long OFF_Z      = OFF_EYE    + (long long)N_ * N_;
constexpr long long OFF_ZPOS   = OFF_Z      + 1;                    // odd -> 4B only
constexpr long long OFF_ADJA   = OFF_ZPOS   + (long long)N_ * N_;   // odd
constexpr long long OFF_WA     = OFF_ADJA   + (long long)N_ * N_;

// Scratch (device globals)
__device__ float g_h   [ROWS * H_];      // h  (row-major, for k1b)
__device__ float g_hT  [H_ * ROWS];      // h^T (B-operand for k3)
__device__ float g_hp  [ROWS * H_];      // elu(attn@h)
__device__ float g_A1T [N_ * N_];        // adj_A1 transposed (A-operand for k5)
__device__ float g_xpwT[O_ * ROWS];      // (x_proj+Wa)^T (B-operand for k5)
__device__ float g_es  [ROWS];
__device__ float g_ed  [ROWS];
__device__ float g_mx  [ROWS];
__device__ float g_rs  [ROWS];

// ---- tf32 mma helpers -----------------------------------------------------
__device__ __forceinline__ unsigned f2tf(float f) {
    unsigned u; asm("cvt.rna.tf32.f32 %0, %1;" : "=r"(u) : "f"(f)); return u;
}
__device__ __forceinline__ void mma8(float* d, const unsigned* a, const unsigned* b) {
    asm volatile("mma.sync.aligned.m16n8k8.row.col.f32.tf32.tf32.f32 "
        "{%0,%1,%2,%3},{%4,%5,%6,%7},{%8,%9},{%0,%1,%2,%3};"
        : "+f"(d[0]), "+f"(d[1]), "+f"(d[2]), "+f"(d[3])
        : "r"(a[0]), "r"(a[1]), "r"(a[2]), "r"(a[3]), "r"(b[0]), "r"(b[1]));
}

// ---------------------------------------------------------------------------
// K0: elementwise outputs (adj_A1, eye, copies)
// ---------------------------------------------------------------------------
__global__ void k0_misc(const float* __restrict__ adjA,
                        const float* __restrict__ zpos,
                        const float* __restrict__ Wa,
                        const float* __restrict__ z,
                        float* __restrict__ out)
{
    int i4 = blockIdx.x * blockDim.x + threadIdx.x;
    if (i4 < (N_ * N_ / 4)) {
        float4 a4  = ((const float4*)adjA)[i4];
        float4 zp4 = ((const float4*)zpos)[i4];
        int g = i4 * 4;
        float* adja_dst = out + OFF_ADJA + g;
        float* zpos_dst = out + OFF_ZPOS + g;
        const float* ap = (const float*)&a4;
        const float* zp = (const float*)&zp4;
#pragma unroll
        for (int l = 0; l < 4; l++) { adja_dst[l] = ap[l]; zpos_dst[l] = zp[l]; }

        float4 s4; float* sp = (float*)&s4;
#pragma unroll
        for (int l = 0; l < 4; l++) {
            float c = fminf(fmaxf(ap[l], -3.f), 3.f);
            float s = sinhf(3.f * c);
            sp[l] = fminf(fmaxf(s, -1000.f), 1000.f);
        }
        ((float4*)(out + OFF_ADJ1))[i4] = s4;

        int row = g >> 11, col = g & 2047;
        float4 e4; float* ep = (float*)&e4;
#pragma unroll
        for (int l = 0; l < 4; l++) ep[l] = (col + l == row) ? 1.f : 0.f;
        ((float4*)(out + OFF_EYE))[i4] = e4;
    }
    if (blockIdx.x == 0) {
        if (threadIdx.x < O_)  out[OFF_WA + threadIdx.x] = Wa[threadIdx.x];
        if (threadIdx.x == O_) out[OFF_Z] = z[0];
    }
}

// ---------------------------------------------------------------------------
// K0b: g_A1T = adj_A1^T  (32x32 smem tiles)
// ---------------------------------------------------------------------------
__global__ __launch_bounds__(256) void k0b_transpose(const float* __restrict__ out)
{
    __shared__ float t[32][33];
    const float* A1 = out + OFF_ADJ1;
    int bx = blockIdx.x;
    int c0 = (bx & 63) * 32;     // m tile (A1 col)
    int r0 = (bx >> 6) * 32;     // n tile (A1 row)
    int tid = threadIdx.x;
    int lr = tid >> 5, lc = tid & 31;
#pragma unroll
    for (int it = 0; it < 4; it++) {
        int row = lr + it * 8;
        t[row][lc] = A1[(long long)(r0 + row) * N_ + c0 + lc];
    }
    __syncthreads();
#pragma unroll
    for (int it = 0; it < 4; it++) {
        int row = lr + it * 8;
        g_A1T[(long long)(c0 + row) * N_ + r0 + lc] = t[lc][row];
    }
}

// ---------------------------------------------------------------------------
// K1: h = x @ W^T -- tf32 mma. block 64m x 128h, 8 warps (2m x 4h).
// A = x [m][k] row-major, B = W [h][k] row-major: both native row.col layouts.
// Writes g_h (row-major) and g_hT (transposed).
// ---------------------------------------------------------------------------
__global__ __launch_bounds__(256) void k1_h(const float* __restrict__ x,
                                            const float* __restrict__ W)
{
    __shared__ unsigned sA[64][36];
    __shared__ unsigned sB[128][36];
    const int m0 = blockIdx.x * 64;
    const int tid = threadIdx.x;
    const int w = tid >> 5, lane = tid & 31;
    const int g = lane >> 2, tg = lane & 3;
    const int mbase = (w >> 2) * 32;
    const int hbase = (w & 3) * 32;

    float acc[2][4][4];
#pragma unroll
    for (int mf = 0; mf < 2; mf++)
#pragma unroll
        for (int nf = 0; nf < 4; nf++)
#pragma unroll
            for (int t = 0; t < 4; t++) acc[mf][nf][t] = 0.f;

    for (int f0 = 0; f0 < F_; f0 += 32) {
#pragma unroll
        for (int it = 0; it < 2; it++) {            // sA: 64x32 (512 float4)
            int idx = tid + it * 256;
            int mi = idx >> 3, k4 = idx & 7;
            float4 v = *(const float4*)&x[(m0 + mi) * F_ + f0 + k4 * 4];
            uint4 u = { f2tf(v.x), f2tf(v.y), f2tf(v.z), f2tf(v.w) };
            *(uint4*)&sA[mi][k4 * 4] = u;
        }
#pragma unroll
        for (int it = 0; it < 4; it++) {            // sB: 128x32 (1024 float4)
            int idx = tid + it * 256;
            int hh = idx >> 3, k4 = idx & 7;
            float4 v = *(const float4*)&W[hh * F_ + f0 + k4 * 4];
            uint4 u = { f2tf(v.x), f2tf(v.y), f2tf(v.z), f2tf(v.w) };
            *(uint4*)&sB[hh][k4 * 4] = u;
        }
        __syncthreads();
#pragma unroll
        for (int ks = 0; ks < 4; ks++) {
            int kb = ks * 8;
            unsigned afr[2][4], bfr[4][2];
#pragma unroll
            for (int mf = 0; mf < 2; mf++) {
                int mr = mbase + mf * 16 + g;
                afr[mf][0] = sA[mr    ][kb + tg];
                afr[mf][1] = sA[mr + 8][kb + tg];
                afr[mf][2] = sA[mr    ][kb + 4 + tg];
                afr[mf][3] = sA[mr + 8][kb + 4 + tg];
            }
#pragma unroll
            for (int nf = 0; nf < 4; nf++) {
                int cc = hbase + nf * 8 + g;
                bfr[nf][0] = sB[cc][kb + tg];
                bfr[nf][1] = sB[cc][kb + 4 + tg];
            }
#pragma unroll
            for (int mf = 0; mf < 2; mf++)
#pragma unroll
                for (int nf = 0; nf < 4; nf++)
                    mma8(acc[mf][nf], afr[mf], bfr[nf]);
        }
        __syncthreads();
    }
#pragma unroll
    for (int mf = 0; mf < 2; mf++) {
#pragma unroll
        for (int nf = 0; nf < 4; nf++) {
            int c = hbase + nf * 8 + 2 * tg;
            int r0 = m0 + mbase + mf * 16 + g;
            int r1 = r0 + 8;
            float v0 = acc[mf][nf][0], v1 = acc[mf][nf][1];
            float v2 = acc[mf][nf][2], v3 = acc[mf][nf][3];
            *(float2*)&g_h[r0 * H_ + c] = make_float2(v0, v1);
            *(float2*)&g_h[r1 * H_ + c] = make_float2(v2, v3);
            g_hT[(long long)c       * ROWS + r0] = v0;
            g_hT[(long long)(c + 1) * ROWS + r0] = v1;
            g_hT[(long long)c       * ROWS + r1] = v2;
            g_hT[(long long)(c + 1) * ROWS + r1] = v3;
        }
    }
}

// ---------------------------------------------------------------------------
// K1b: e_src / e_dst (one warp per row)
// ---------------------------------------------------------------------------
__global__ void k1b_e(const float* __restrict__ a_src,
                      const float* __restrict__ a_dst)
{
    int warp = threadIdx.x >> 5, lane = threadIdx.x & 31;
    int r = blockIdx.x * 8 + warp;
    float s1 = 0.f, s2 = 0.f;
#pragma unroll
    for (int t = 0; t < 4; t++) {
        int h = lane + 32 * t;
        float v = g_h[r * H_ + h];
        s1 += v * a_src[h];
        s2 += v * a_dst[h];
    }
#pragma unroll
    for (int off = 16; off >= 1; off >>= 1) {
        s1 += __shfl_xor_sync(0xffffffffu, s1, off);
        s2 += __shfl_xor_sync(0xffffffffu, s2, off);
    }
    if (lane == 0) { g_es[r] = s1; g_ed[r] = s2; }
}

// ---------------------------------------------------------------------------
// K2: softmax row stats. Mask shared across batches; scores cached in regs
// between the max pass and the sum pass (ed/mask read once).
// ---------------------------------------------------------------------------
__global__ __launch_bounds__(256) void k2_stats(const float* __restrict__ adjA)
{
    __shared__ unsigned char msk[N_];
    const int m = blockIdx.x;
    const int tid = threadIdx.x;
    const int warp = tid >> 5, lane = tid & 31;
#pragma unroll
    for (int it = 0; it < 8; it++) {
        int n = tid + it * 256;
        float adj = adjA[(long long)m * N_ + n] + (n == m ? 1.f : 0.f);
        msk[n] = (adj <= 0.f) ? 1 : 0;
    }
    __syncthreads();

    const int b = warp;
    const int r = b * N_ + m;
    const float es = g_es[r];
    const float* edb = g_ed + b * N_;

    float sc[64];
    float mx = -INFINITY;
#pragma unroll
    for (int t = 0; t < 64; t++) {
        int n = lane + 32 * t;
        float v = es + edb[n];
        float lr = fmaxf(v, 0.2f * v);
        float s = msk[n] ? NEG_INF : lr;
        sc[t] = s;
        mx = fmaxf(mx, s);
    }
#pragma unroll
    for (int off = 16; off >= 1; off >>= 1)
        mx = fmaxf(mx, __shfl_xor_sync(0xffffffffu, mx, off));

    float sm = 0.f;
#pragma unroll
    for (int t = 0; t < 64; t++) sm += __expf(sc[t] - mx);
#pragma unroll
    for (int off = 16; off >= 1; off >>= 1)
        sm += __shfl_xor_sync(0xffffffffu, sm, off);

    if (lane == 0) { g_mx[r] = mx; g_rs[r] = 1.f / sm; }
}

// ---------------------------------------------------------------------------
// K3: h_prime = elu(attn @ h) -- tf32 mma.sync.m16n8k8
// ---------------------------------------------------------------------------
__global__ __launch_bounds__(256) void k3_attn(const float* __restrict__ adjA)
{
    __shared__ unsigned w_s[64][36];     // A tile, tf32 bits
    __shared__ unsigned sB [128][36];    // B^T tile (h cols x k), tf32 bits
    __shared__ float s_mx[64], s_rs[64], s_es[64];

    const int b  = blockIdx.x >> 5;
    const int m0 = (blockIdx.x & 31) * 64;
    const int rbase = b * N_ + m0;
    const int tid = threadIdx.x;
    const int w = tid >> 5, lane = tid & 31;
    const int g = lane >> 2, tg = lane & 3;
    const int mbase = (w >> 2) * 32;
    const int hbase = (w & 3) * 32;

    if (tid < 64) {
        s_mx[tid] = g_mx[rbase + tid];
        s_rs[tid] = g_rs[rbase + tid];
        s_es[tid] = g_es[rbase + tid];
    }
    __syncthreads();

    float acc[2][4][4];
#pragma unroll
    for (int mf = 0; mf < 2; mf++)
#pragma unroll
        for (int nf = 0; nf < 4; nf++)
#pragma unroll
            for (int t = 0; t < 4; t++) acc[mf][nf][t] = 0.f;

    const int mi = tid >> 2;
    const int nb = (tid & 3) * 8;
    const int gm = m0 + mi;
    const float* arow = adjA + (long long)gm * N_;
    const float* edb  = g_ed + b * N_;
    const float es = s_es[mi], mxv = s_mx[mi], rs = s_rs[mi];

    for (int n0 = 0; n0 < N_; n0 += 32) {
#pragma unroll
        for (int it = 0; it < 4; it++) {
            int idx = tid + it * 256;
            int c = idx >> 3, kk4 = idx & 7;
            float4 v = *(const float4*)&g_hT[(long long)c * ROWS + b * N_ + n0 + kk4 * 4];
            uint4 u = { f2tf(v.x), f2tf(v.y), f2tf(v.z), f2tf(v.w) };
            *(uint4*)&sB[c][kk4 * 4] = u;
        }
        {
            float4 a4[2], e4[2];
            a4[0] = *(const float4*)(arow + n0 + nb);
            a4[1] = *(const float4*)(arow + n0 + nb + 4);
            e4[0] = *(const float4*)(edb  + n0 + nb);
            e4[1] = *(const float4*)(edb  + n0 + nb + 4);
            const float* ap = (const float*)a4;
            const float* ep = (const float*)e4;
#pragma unroll
            for (int jj = 0; jj < 8; jj++) {
                int n = n0 + nb + jj;
                float adj = ap[jj] + (n == gm ? 1.f : 0.f);
                float t = es + ep[jj];
                float lr = fmaxf(t, 0.2f * t);
                float sc = (adj <= 0.f) ? NEG_INF : lr;
                w_s[mi][nb + jj] = f2tf(__expf(sc - mxv) * rs);
            }
        }
        __syncthreads();

#pragma unroll
        for (int ks = 0; ks < 4; ks++) {
            int kb = ks * 8;
            unsigned afr[2][4], bfr[4][2];
#pragma unroll
            for (int mf = 0; mf < 2; mf++) {
                int mr = mbase + mf * 16 + g;
                afr[mf][0] = w_s[mr    ][kb + tg];
                afr[mf][1] = w_s[mr + 8][kb + tg];
                afr[mf][2] = w_s[mr    ][kb + 4 + tg];
                afr[mf][3] = w_s[mr + 8][kb + 4 + tg];
            }
#pragma unroll
            for (int nf = 0; nf < 4; nf++) {
                int cc = hbase + nf * 8 + g;
                bfr[nf][0] = sB[cc][kb + tg];
                bfr[nf][1] = sB[cc][kb + 4 + tg];
            }
#pragma unroll
            for (int mf = 0; mf < 2; mf++)
#pragma unroll
                for (int nf = 0; nf < 4; nf++)
                    mma8(acc[mf][nf], afr[mf], bfr[nf]);
        }
        __syncthreads();
    }

#pragma unroll
    for (int mf = 0; mf < 2; mf++) {
#pragma unroll
        for (int nf = 0; nf < 4; nf++) {
            int c = hbase + nf * 8 + 2 * tg;
            int r0 = rbase + mbase + mf * 16 + g;
            int r1 = r0 + 8;
            float2 lo, hi;
            float v0 = acc[mf][nf][0], v1 = acc[mf][nf][1];
            float v2 = acc[mf][nf][2], v3 = acc[mf][nf][3];
            lo.x = v0 > 0.f ? v0 : expm1f(v0);
            lo.y = v1 > 0.f ? v1 : expm1f(v1);
            hi.x = v2 > 0.f ? v2 : expm1f(v2);
            hi.y = v3 > 0.f ? v3 : expm1f(v3);
            *(float2*)&g_hp[r0 * H_ + c] = lo;
            *(float2*)&g_hp[r1 * H_ + c] = hi;
        }
    }
}

// ---------------------------------------------------------------------------
// K4: x_proj = hp @ fc2_w^T + fc2_b -- tf32 mma. block 128m x 64o,
// 8 warps (4m x 2o). A = g_hp [m][k], B = fc2w [o][k]. Writes g_xpwT too.
// ---------------------------------------------------------------------------
__global__ __launch_bounds__(256) void k4_xproj(const float* __restrict__ fc2w,
                                                const float* __restrict__ fc2b,
                                                const float* __restrict__ Wa,
                                                float* __restrict__ out)
{
    __shared__ unsigned sA[128][36];
    __shared__ unsigned sB[64][36];
    const int m0 = blockIdx.x * 128;
    const int tid = threadIdx.x;
    const int w = tid >> 5, lane = tid & 31;
    const int g = lane >> 2, tg = lane & 3;
    const int mbase = (w >> 1) * 32;
    const int obase = (w & 1) * 32;

    float acc[2][4][4];
#pragma unroll
    for (int mf = 0; mf < 2; mf++)
#pragma unroll
        for (int nf = 0; nf < 4; nf++)
#pragma unroll
            for (int t = 0; t < 4; t++) acc[mf][nf][t] = 0.f;

    for (int f0 = 0; f0 < H_; f0 += 32) {
#pragma unroll
        for (int it = 0; it < 4; it++) {            // sA: 128x32
            int idx = tid + it * 256;
            int mi = idx >> 3, k4 = idx & 7;
            float4 v = *(const float4*)&g_hp[(m0 + mi) * H_ + f0 + k4 * 4];
            uint4 u = { f2tf(v.x), f2tf(v.y), f2tf(v.z), f2tf(v.w) };
            *(uint4*)&sA[mi][k4 * 4] = u;
        }
#pragma unroll
        for (int it = 0; it < 2; it++) {            // sB: 64x32
            int idx = tid + it * 256;
            int o = idx >> 3, k4 = idx & 7;
            float4 v = *(const float4*)&fc2w[o * H_ + f0 + k4 * 4];
            uint4 u = { f2tf(v.x), f2tf(v.y), f2tf(v.z), f2tf(v.w) };
            *(uint4*)&sB[o][k4 * 4] = u;
        }
        __syncthreads();
#pragma unroll
        for (int ks = 0; ks < 4; ks++) {
            int kb = ks * 8;
            unsigned afr[2][4], bfr[4][2];
#pragma unroll
            for (int mf = 0; mf < 2; mf++) {
                int mr = mbase + mf * 16 + g;
                afr[mf][0] = sA[mr    ][kb + tg];
                afr[mf][1] = sA[mr + 8][kb + tg];
                afr[mf][2] = sA[mr    ][kb + 4 + tg];
                afr[mf][3] = sA[mr + 8][kb + 4 + tg];
            }
#pragma unroll
            for (int nf = 0; nf < 4; nf++) {
                int oc = obase + nf * 8 + g;
                bfr[nf][0] = sB[oc][kb + tg];
                bfr[nf][1] = sB[oc][kb + 4 + tg];
            }
#pragma unroll
            for (int mf = 0; mf < 2; mf++)
#pragma unroll
                for (int nf = 0; nf < 4; nf++)
                    mma8(acc[mf][nf], afr[mf], bfr[nf]);
        }
        __syncthreads();
    }
#pragma unroll
    for (int mf = 0; mf < 2; mf++) {
#pragma unroll
        for (int nf = 0; nf < 4; nf++) {
            int c = obase + nf * 8 + 2 * tg;
            int r0 = m0 + mbase + mf * 16 + g;
            int r1 = r0 + 8;
            float b0 = fc2b[c], b1 = fc2b[c + 1];
            float w0 = Wa[c],   w1 = Wa[c + 1];
            float v0 = acc[mf][nf][0] + b0, v1 = acc[mf][nf][1] + b1;
            float v2 = acc[mf][nf][2] + b0, v3 = acc[mf][nf][3] + b1;
            *(float2*)&out[OFF_XPROJ + (long long)r0 * O_ + c] = make_float2(v0, v1);
            *(float2*)&out[OFF_XPROJ + (long long)r1 * O_ + c] = make_float2(v2, v3);
            g_xpwT[(long long)c       * ROWS + r0] = v0 + w0;
            g_xpwT[(long long)(c + 1) * ROWS + r0] = v1 + w1;
            g_xpwT[(long long)c       * ROWS + r1] = v2 + w0;
            g_xpwT[(long long)(c + 1) * ROWS + r1] = v3 + w1;
        }
    }
}

// ---------------------------------------------------------------------------
// K5: logits = x_proj - A1^T @ xpw -- tf32 mma
// ---------------------------------------------------------------------------
__global__ __launch_bounds__(256) void k5_logits(float* __restrict__ out)
{
    __shared__ unsigned sA[128][36];
    __shared__ unsigned sB[64][36];
    const int b  = blockIdx.x >> 4;
    const int m0 = (blockIdx.x & 15) * 128;
    const int tid = threadIdx.x;
    const int w = tid >> 5, lane = tid & 31;
    const int g = lane >> 2, tg = lane & 3;
    const int mbase = (w >> 1) * 32;
    const int obase = (w & 1) * 32;

    float acc[2][4][4];
#pragma unroll
    for (int mf = 0; mf < 2; mf++)
#pragma unroll
        for (int nf = 0; nf < 4; nf++)
#pragma unroll
            for (int t = 0; t < 4; t++) acc[mf][nf][t] = 0.f;

    for (int n0 = 0; n0 < N_; n0 += 32) {
#pragma unroll
        for (int it = 0; it < 4; it++) {            // sA: 128x32
            int idx = tid + it * 256;
            int m = idx >> 3, kk4 = idx & 7;
            float4 v = *(const float4*)&g_A1T[(long long)(m0 + m) * N_ + n0 + kk4 * 4];
            uint4 u = { f2tf(v.x), f2tf(v.y), f2tf(v.z), f2tf(v.w) };
            *(uint4*)&sA[m][kk4 * 4] = u;
        }
#pragma unroll
        for (int it = 0; it < 2; it++) {            // sB: 64x32
            int idx = tid + it * 256;
            int o = idx >> 3, kk4 = idx & 7;
            float4 v = *(const float4*)&g_xpwT[(long long)o * ROWS + b * N_ + n0 + kk4 * 4];
            uint4 u = { f2tf(v.x), f2tf(v.y), f2tf(v.z), f2tf(v.w) };
            *(uint4*)&sB[o][kk4 * 4] = u;
        }
        __syncthreads();

#pragma unroll
        for (int ks = 0; ks < 4; ks++) {
            int kb = ks * 8;
            unsigned afr[2][4], bfr[4][2];
#pragma unroll
            for (int mf = 0; mf < 2; mf++) {
                int mr = mbase + mf * 16 + g;
                afr[mf][0] = sA[mr    ][kb + tg];
                afr[mf][1] = sA[mr + 8][kb + tg];
                afr[mf][2] = sA[mr    ][kb + 4 + tg];
                afr[mf][3] = sA[mr + 8][kb + 4 + tg];
            }
#pragma unroll
            for (int nf = 0; nf < 4; nf++) {
                int oc = obase + nf * 8 + g;
                bfr[nf][0] = sB[oc][kb + tg];
                bfr[nf][1] = sB[oc][kb + 4 + tg];
            }
#pragma unroll
            for (int mf = 0; mf < 2; mf++)
#pragma unroll
                for (int nf = 0; nf < 4; nf++)
                    mma8(acc[mf][nf], afr[mf], bfr[nf]);
        }
        __syncthreads();
    }

#pragma unroll
    for (int mf = 0; mf < 2; mf++) {
#pragma unroll
        for (int nf = 0; nf < 4; nf++) {
            int c = obase + nf * 8 + 2 * tg;
            int r0 = b * N_ + m0 + mbase + mf * 16 + g;
            int r1 = r0 + 8;
            float2 xp0 = *(const float2*)&out[OFF_XPROJ + (long long)r0 * O_ + c];
            float2 xp1 = *(const float2*)&out[OFF_XPROJ + (long long)r1 * O_ + c];
            float2 o0, o1;
            o0.x = xp0.x - acc[mf][nf][0]; o0.y = xp0.y - acc[mf][nf][1];
            o1.x = xp1.x - acc[mf][nf][2]; o1.y = xp1.y - acc[mf][nf][3];
            *(float2*)&out[OFF_LOGITS + (long long)r0 * O_ + c] = o0;
            *(float2*)&out[OFF_LOGITS + (long long)r1 * O_ + c] = o1;
        }
    }
}

// ---------------------------------------------------------------------------
extern "C" void kernel_launch(void* const* d_in, const int* in_sizes, int n_in,
                              void* d_out, int out_size)
{
    const float* x     = (const float*)d_in[0];
    const float* adjA  = (const float*)d_in[1];
    const float* W     = (const float*)d_in[2];
    const float* a_src = (const float*)d_in[3];
    const float* a_dst = (const float*)d_in[4];
    const float* fc2w  = (const float*)d_in[5];
    const float* fc2b  = (const float*)d_in[6];
    const float* Wa    = (const float*)d_in[7];
    const float* z     = (const float*)d_in[8];
    const float* zpos  = (const float*)d_in[9];
    float* out = (float*)d_out;

    k0_misc      <<<(N_ * N_ / 4 + 255) / 256, 256>>>(adjA, zpos, Wa, z, out);
    k0b_transpose<<<64 * 64, 256>>>(out);
    k1_h         <<<ROWS / 64, 256>>>(x, W);
    k1b_e        <<<ROWS / 8, 256>>>(a_src, a_dst);
    k2_stats     <<<N_, 256>>>(adjA);
    k3_attn      <<<B_ * (N_ / 64), 256>>>(adjA);
    k4_xproj     <<<ROWS / 128, 256>>>(fc2w, fc2b, Wa, out);
    k5_logits    <<<B_ * (N_ / 128), 256>>>(out);
}

// round 11
// speedup vs baseline: 2.6000x; 1.2401x over previous
#include <cuda_runtime.h>
#include <math.h>

// Problem constants
constexpr int B_ = 8, N_ = 2048, F_ = 128, H_ = 128, O_ = 64;
constexpr int ROWS = B_ * N_;            // 16384
constexpr float NEG_INF = -1.0e9f;

// Output layout (tuple flattened in order)
constexpr long long OFF_XPROJ  = 0;
constexpr long long OFF_LOGITS = OFF_XPROJ  + (long long)B_ * N_ * O_;
constexpr long long OFF_ADJ1   = OFF_LOGITS + (long long)B_ * N_ * O_;
constexpr long long OFF_EYE    = OFF_ADJ1   + (long long)N_ * N_;
constexpr long long OFF_Z      = OFF_EYE    + (long long)N_ * N_;
constexpr long long OFF_ZPOS   = OFF_Z      + 1;                    // odd -> 4B only
constexpr long long OFF_ADJA   = OFF_ZPOS   + (long long)N_ * N_;   // odd
constexpr long long OFF_WA     = OFF_ADJA   + (long long)N_ * N_;

// Scratch (device globals). *t arrays hold tf32 bit patterns.
__device__ float    g_h    [ROWS * H_];   // h row-major (for k1b)
__device__ unsigned g_hTt  [H_ * ROWS];   // tf32(h^T)       (B-operand k3)
__device__ float    g_hp   [ROWS * H_];   // elu(attn@h)
__device__ unsigned g_A1T  [N_ * N_];     // tf32(adj_A1^T)  (A-operand k5)
__device__ unsigned g_xpwTt[O_ * ROWS];   // tf32((xp+Wa)^T) (B-operand k5)
__device__ float    g_es   [ROWS];
__device__ float    g_ed   [ROWS];
__device__ float    g_mx   [ROWS];
__device__ float    g_rs   [ROWS];

// ---- tf32 mma helpers -----------------------------------------------------
__device__ __forceinline__ unsigned f2tf(float f) {
    unsigned u; asm("cvt.rna.tf32.f32 %0, %1;" : "=r"(u) : "f"(f)); return u;
}
__device__ __forceinline__ void mma8(float* d, const unsigned* a, const unsigned* b) {
    asm volatile("mma.sync.aligned.m16n8k8.row.col.f32.tf32.tf32.f32 "
        "{%0,%1,%2,%3},{%4,%5,%6,%7},{%8,%9},{%0,%1,%2,%3};"
        : "+f"(d[0]), "+f"(d[1]), "+f"(d[2]), "+f"(d[3])
        : "r"(a[0]), "r"(a[1]), "r"(a[2]), "r"(a[3]), "r"(b[0]), "r"(b[1]));
}
__device__ __forceinline__ unsigned smem_u32(const void* p) {
    return (unsigned)__cvta_generic_to_shared(p);
}
__device__ __forceinline__ void ldm_x4(unsigned& r0, unsigned& r1,
                                       unsigned& r2, unsigned& r3, unsigned addr) {
    asm volatile("ldmatrix.sync.aligned.m8n8.x4.shared.b16 {%0,%1,%2,%3}, [%4];"
        : "=r"(r0), "=r"(r1), "=r"(r2), "=r"(r3) : "r"(addr));
}

// ---------------------------------------------------------------------------
// K0: elementwise outputs (adj_A1, eye, copies)
// ---------------------------------------------------------------------------
__global__ void k0_misc(const float* __restrict__ adjA,
                        const float* __restrict__ zpos,
                        const float* __restrict__ Wa,
                        const float* __restrict__ z,
                        float* __restrict__ out)
{
    int i4 = blockIdx.x * blockDim.x + threadIdx.x;
    if (i4 < (N_ * N_ / 4)) {
        float4 a4  = ((const float4*)adjA)[i4];
        float4 zp4 = ((const float4*)zpos)[i4];
        int g = i4 * 4;
        float* adja_dst = out + OFF_ADJA + g;
        float* zpos_dst = out + OFF_ZPOS + g;
        const float* ap = (const float*)&a4;
        const float* zp = (const float*)&zp4;
#pragma unroll
        for (int l = 0; l < 4; l++) { adja_dst[l] = ap[l]; zpos_dst[l] = zp[l]; }

        float4 s4; float* sp = (float*)&s4;
#pragma unroll
        for (int l = 0; l < 4; l++) {
            float c = fminf(fmaxf(ap[l], -3.f), 3.f);
            float s = sinhf(3.f * c);
            sp[l] = fminf(fmaxf(s, -1000.f), 1000.f);
        }
        ((float4*)(out + OFF_ADJ1))[i4] = s4;

        int row = g >> 11, col = g & 2047;
        float4 e4; float* ep = (float*)&e4;
#pragma unroll
        for (int l = 0; l < 4; l++) ep[l] = (col + l == row) ? 1.f : 0.f;
        ((float4*)(out + OFF_EYE))[i4] = e4;
    }
    if (blockIdx.x == 0) {
        if (threadIdx.x < O_)  out[OFF_WA + threadIdx.x] = Wa[threadIdx.x];
        if (threadIdx.x == O_) out[OFF_Z] = z[0];
    }
}

// ---------------------------------------------------------------------------
// K0b: g_A1T = tf32(adj_A1^T)  (32x32 smem tiles)
// ---------------------------------------------------------------------------
__global__ __launch_bounds__(256) void k0b_transpose(const float* __restrict__ out)
{
    __shared__ float t[32][33];
    const float* A1 = out + OFF_ADJ1;
    int bx = blockIdx.x;
    int c0 = (bx & 63) * 32;     // m tile (A1 col)
    int r0 = (bx >> 6) * 32;     // n tile (A1 row)
    int tid = threadIdx.x;
    int lr = tid >> 5, lc = tid & 31;
#pragma unroll
    for (int it = 0; it < 4; it++) {
        int row = lr + it * 8;
        t[row][lc] = A1[(long long)(r0 + row) * N_ + c0 + lc];
    }
    __syncthreads();
#pragma unroll
    for (int it = 0; it < 4; it++) {
        int row = lr + it * 8;
        g_A1T[(long long)(c0 + row) * N_ + r0 + lc] = f2tf(t[lc][row]);
    }
}

// ---------------------------------------------------------------------------
// K1: h = x @ W^T -- tf32 mma. block 64m x 128h, 8 warps (2m x 4h).
// Writes g_h (float) and g_hTt (tf32 bits, transposed).
// ---------------------------------------------------------------------------
__global__ __launch_bounds__(256) void k1_h(const float* __restrict__ x,
                                            const float* __restrict__ W)
{
    __shared__ unsigned sA[64][36];
    __shared__ unsigned sB[128][36];
    const int m0 = blockIdx.x * 64;
    const int tid = threadIdx.x;
    const int w = tid >> 5, lane = tid & 31;
    const int g = lane >> 2, tg = lane & 3;
    const int mbase = (w >> 2) * 32;
    const int hbase = (w & 3) * 32;

    float acc[2][4][4];
#pragma unroll
    for (int mf = 0; mf < 2; mf++)
#pragma unroll
        for (int nf = 0; nf < 4; nf++)
#pragma unroll
            for (int t = 0; t < 4; t++) acc[mf][nf][t] = 0.f;

    for (int f0 = 0; f0 < F_; f0 += 32) {
#pragma unroll
        for (int it = 0; it < 2; it++) {            // sA: 64x32
            int idx = tid + it * 256;
            int mi = idx >> 3, k4 = idx & 7;
            float4 v = *(const float4*)&x[(m0 + mi) * F_ + f0 + k4 * 4];
            uint4 u = { f2tf(v.x), f2tf(v.y), f2tf(v.z), f2tf(v.w) };
            *(uint4*)&sA[mi][k4 * 4] = u;
        }
#pragma unroll
        for (int it = 0; it < 4; it++) {            // sB: 128x32
            int idx = tid + it * 256;
            int hh = idx >> 3, k4 = idx & 7;
            float4 v = *(const float4*)&W[hh * F_ + f0 + k4 * 4];
            uint4 u = { f2tf(v.x), f2tf(v.y), f2tf(v.z), f2tf(v.w) };
            *(uint4*)&sB[hh][k4 * 4] = u;
        }
        __syncthreads();
#pragma unroll
        for (int ks = 0; ks < 4; ks++) {
            int kb = ks * 8;
            unsigned afr[2][4], bfr[4][2];
#pragma unroll
            for (int mf = 0; mf < 2; mf++) {
                int mr = mbase + mf * 16 + g;
                afr[mf][0] = sA[mr    ][kb + tg];
                afr[mf][1] = sA[mr + 8][kb + tg];
                afr[mf][2] = sA[mr    ][kb + 4 + tg];
                afr[mf][3] = sA[mr + 8][kb + 4 + tg];
            }
#pragma unroll
            for (int nf = 0; nf < 4; nf++) {
                int cc = hbase + nf * 8 + g;
                bfr[nf][0] = sB[cc][kb + tg];
                bfr[nf][1] = sB[cc][kb + 4 + tg];
            }
#pragma unroll
            for (int mf = 0; mf < 2; mf++)
#pragma unroll
                for (int nf = 0; nf < 4; nf++)
                    mma8(acc[mf][nf], afr[mf], bfr[nf]);
        }
        __syncthreads();
    }
#pragma unroll
    for (int mf = 0; mf < 2; mf++) {
#pragma unroll
        for (int nf = 0; nf < 4; nf++) {
            int c = hbase + nf * 8 + 2 * tg;
            int r0 = m0 + mbase + mf * 16 + g;
            int r1 = r0 + 8;
            float v0 = acc[mf][nf][0], v1 = acc[mf][nf][1];
            float v2 = acc[mf][nf][2], v3 = acc[mf][nf][3];
            *(float2*)&g_h[r0 * H_ + c] = make_float2(v0, v1);
            *(float2*)&g_h[r1 * H_ + c] = make_float2(v2, v3);
            g_hTt[(long long)c       * ROWS + r0] = f2tf(v0);
            g_hTt[(long long)(c + 1) * ROWS + r0] = f2tf(v1);
            g_hTt[(long long)c       * ROWS + r1] = f2tf(v2);
            g_hTt[(long long)(c + 1) * ROWS + r1] = f2tf(v3);
        }
    }
}

// ---------------------------------------------------------------------------
// K1b: e_src / e_dst (one warp per row)
// ---------------------------------------------------------------------------
__global__ void k1b_e(const float* __restrict__ a_src,
                      const float* __restrict__ a_dst)
{
    int warp = threadIdx.x >> 5, lane = threadIdx.x & 31;
    int r = blockIdx.x * 8 + warp;
    float s1 = 0.f, s2 = 0.f;
#pragma unroll
    for (int t = 0; t < 4; t++) {
        int h = lane + 32 * t;
        float v = g_h[r * H_ + h];
        s1 += v * a_src[h];
        s2 += v * a_dst[h];
    }
#pragma unroll
    for (int off = 16; off >= 1; off >>= 1) {
        s1 += __shfl_xor_sync(0xffffffffu, s1, off);
        s2 += __shfl_xor_sync(0xffffffffu, s2, off);
    }
    if (lane == 0) { g_es[r] = s1; g_ed[r] = s2; }
}

// ---------------------------------------------------------------------------
// K2: softmax row stats (mask shared across batches, scores reg-cached)
// ---------------------------------------------------------------------------
__global__ __launch_bounds__(256) void k2_stats(const float* __restrict__ adjA)
{
    __shared__ unsigned char msk[N_];
    const int m = blockIdx.x;
    const int tid = threadIdx.x;
    const int warp = tid >> 5, lane = tid & 31;
#pragma unroll
    for (int it = 0; it < 8; it++) {
        int n = tid + it * 256;
        float adj = adjA[(long long)m * N_ + n] + (n == m ? 1.f : 0.f);
        msk[n] = (adj <= 0.f) ? 1 : 0;
    }
    __syncthreads();

    const int b = warp;
    const int r = b * N_ + m;
    const float es = g_es[r];
    const float* edb = g_ed + b * N_;

    float sc[64];
    float mx = -INFINITY;
#pragma unroll
    for (int t = 0; t < 64; t++) {
        int n = lane + 32 * t;
        float v = es + edb[n];
        float lr = fmaxf(v, 0.2f * v);
        float s = msk[n] ? NEG_INF : lr;
        sc[t] = s;
        mx = fmaxf(mx, s);
    }
#pragma unroll
    for (int off = 16; off >= 1; off >>= 1)
        mx = fmaxf(mx, __shfl_xor_sync(0xffffffffu, mx, off));

    float sm = 0.f;
#pragma unroll
    for (int t = 0; t < 64; t++) sm += __expf(sc[t] - mx);
#pragma unroll
    for (int off = 16; off >= 1; off >>= 1)
        sm += __shfl_xor_sync(0xffffffffu, sm, off);

    if (lane == 0) { g_mx[r] = mx; g_rs[r] = 1.f / sm; }
}

// ---------------------------------------------------------------------------
// K3: h_prime = elu(attn @ h) -- tf32 mma + ldmatrix fragments.
// block: 64m x 128h, 8 warps (2m x 4h). B tile pre-converted (g_hTt).
// ---------------------------------------------------------------------------
__global__ __launch_bounds__(256) void k3_attn(const float* __restrict__ adjA)
{
    __shared__ unsigned w_s[64][36];     // A tile (attn weights, tf32 bits)
    __shared__ unsigned sB [128][36];    // B^T tile (tf32 bits)
    __shared__ float s_mx[64], s_rs[64], s_es[64];

    const int b  = blockIdx.x >> 5;
    const int m0 = (blockIdx.x & 31) * 64;
    const int rbase = b * N_ + m0;
    const int tid = threadIdx.x;
    const int w = tid >> 5, lane = tid & 31;
    const int g = lane >> 2, tg = lane & 3;
    const int mbase = (w >> 2) * 32;
    const int hbase = (w & 3) * 32;

    if (tid < 64) {
        s_mx[tid] = g_mx[rbase + tid];
        s_rs[tid] = g_rs[rbase + tid];
        s_es[tid] = g_es[rbase + tid];
    }

    // ldmatrix per-lane base addresses (ks = 0)
    unsigned aBase[2], bBase[2];
#pragma unroll
    for (int mf = 0; mf < 2; mf++)
        aBase[mf] = smem_u32(&w_s[mbase + mf * 16 + (lane & 15)][4 * (lane >> 4)]);
#pragma unroll
    for (int p = 0; p < 2; p++)
        bBase[p] = smem_u32(&sB[hbase + (2 * p + (lane >> 4)) * 8 + (lane & 7)]
                               [4 * ((lane >> 3) & 1)]);
    __syncthreads();

    float acc[2][4][4];
#pragma unroll
    for (int mf = 0; mf < 2; mf++)
#pragma unroll
        for (int nf = 0; nf < 4; nf++)
#pragma unroll
            for (int t = 0; t < 4; t++) acc[mf][nf][t] = 0.f;

    const int mi = tid >> 2;
    const int nb = (tid & 3) * 8;
    const int gm = m0 + mi;
    const float* arow = adjA + (long long)gm * N_;
    const float* edb  = g_ed + b * N_;
    const float es = s_es[mi], mxv = s_mx[mi], rs = s_rs[mi];

    for (int n0 = 0; n0 < N_; n0 += 32) {
        // B^T tile: raw copy of pre-converted tf32 bits
#pragma unroll
        for (int it = 0; it < 4; it++) {
            int idx = tid + it * 256;
            int c = idx >> 3, kk4 = idx & 7;
            *(uint4*)&sB[c][kk4 * 4] =
                *(const uint4*)&g_hTt[(long long)c * ROWS + b * N_ + n0 + kk4 * 4];
        }
        // attn weights for this 64x32 tile
        {
            float4 a4[2], e4[2];
            a4[0] = *(const float4*)(arow + n0 + nb);
            a4[1] = *(const float4*)(arow + n0 + nb + 4);
            e4[0] = *(const float4*)(edb  + n0 + nb);
            e4[1] = *(const float4*)(edb  + n0 + nb + 4);
            const float* ap = (const float*)a4;
            const float* ep = (const float*)e4;
#pragma unroll
            for (int jj = 0; jj < 8; jj++) {
                int n = n0 + nb + jj;
                float adj = ap[jj] + (n == gm ? 1.f : 0.f);
                float t = es + ep[jj];
                float lr = fmaxf(t, 0.2f * t);
                float sc = (adj <= 0.f) ? NEG_INF : lr;
                w_s[mi][nb + jj] = f2tf(__expf(sc - mxv) * rs);
            }
        }
        __syncthreads();

#pragma unroll
        for (int ks = 0; ks < 4; ks++) {
            unsigned afr[2][4], bfr[4][2];
            ldm_x4(afr[0][0], afr[0][1], afr[0][2], afr[0][3], aBase[0] + ks * 32);
            ldm_x4(afr[1][0], afr[1][1], afr[1][2], afr[1][3], aBase[1] + ks * 32);
            ldm_x4(bfr[0][0], bfr[0][1], bfr[1][0], bfr[1][1], bBase[0] + ks * 32);
            ldm_x4(bfr[2][0], bfr[2][1], bfr[3][0], bfr[3][1], bBase[1] + ks * 32);
#pragma unroll
            for (int mf = 0; mf < 2; mf++)
#pragma unroll
                for (int nf = 0; nf < 4; nf++)
                    mma8(acc[mf][nf], afr[mf], bfr[nf]);
        }
        __syncthreads();
    }

#pragma unroll
    for (int mf = 0; mf < 2; mf++) {
#pragma unroll
        for (int nf = 0; nf < 4; nf++) {
            int c = hbase + nf * 8 + 2 * tg;
            int r0 = rbase + mbase + mf * 16 + g;
            int r1 = r0 + 8;
            float2 lo, hi;
            float v0 = acc[mf][nf][0], v1 = acc[mf][nf][1];
            float v2 = acc[mf][nf][2], v3 = acc[mf][nf][3];
            lo.x = v0 > 0.f ? v0 : expm1f(v0);
            lo.y = v1 > 0.f ? v1 : expm1f(v1);
            hi.x = v2 > 0.f ? v2 : expm1f(v2);
            hi.y = v3 > 0.f ? v3 : expm1f(v3);
            *(float2*)&g_hp[r0 * H_ + c] = lo;
            *(float2*)&g_hp[r1 * H_ + c] = hi;
        }
    }
}

// ---------------------------------------------------------------------------
// K4: x_proj = hp @ fc2_w^T + fc2_b -- tf32 mma. block 128m x 64o,
// 8 warps (4m x 2o). Writes g_xpwTt (tf32 bits, transposed).
// ---------------------------------------------------------------------------
__global__ __launch_bounds__(256) void k4_xproj(const float* __restrict__ fc2w,
                                                const float* __restrict__ fc2b,
                                                const float* __restrict__ Wa,
                                                float* __restrict__ out)
{
    __shared__ unsigned sA[128][36];
    __shared__ unsigned sB[64][36];
    const int m0 = blockIdx.x * 128;
    const int tid = threadIdx.x;
    const int w = tid >> 5, lane = tid & 31;
    const int g = lane >> 2, tg = lane & 3;
    const int mbase = (w >> 1) * 32;
    const int obase = (w & 1) * 32;

    float acc[2][4][4];
#pragma unroll
    for (int mf = 0; mf < 2; mf++)
#pragma unroll
        for (int nf = 0; nf < 4; nf++)
#pragma unroll
            for (int t = 0; t < 4; t++) acc[mf][nf][t] = 0.f;

    for (int f0 = 0; f0 < H_; f0 += 32) {
#pragma unroll
        for (int it = 0; it < 4; it++) {            // sA: 128x32
            int idx = tid + it * 256;
            int mi = idx >> 3, k4 = idx & 7;
            float4 v = *(const float4*)&g_hp[(m0 + mi) * H_ + f0 + k4 * 4];
            uint4 u = { f2tf(v.x), f2tf(v.y), f2tf(v.z), f2tf(v.w) };
            *(uint4*)&sA[mi][k4 * 4] = u;
        }
#pragma unroll
        for (int it = 0; it < 2; it++) {            // sB: 64x32
            int idx = tid + it * 256;
            int o = idx >> 3, k4 = idx & 7;
            float4 v = *(const float4*)&fc2w[o * H_ + f0 + k4 * 4];
            uint4 u = { f2tf(v.x), f2tf(v.y), f2tf(v.z), f2tf(v.w) };
            *(uint4*)&sB[o][k4 * 4] = u;
        }
        __syncthreads();
#pragma unroll
        for (int ks = 0; ks < 4; ks++) {
            int kb = ks * 8;
            unsigned afr[2][4], bfr[4][2];
#pragma unroll
            for (int mf = 0; mf < 2; mf++) {
                int mr = mbase + mf * 16 + g;
                afr[mf][0] = sA[mr    ][kb + tg];
                afr[mf][1] = sA[mr + 8][kb + tg];
                afr[mf][2] = sA[mr    ][kb + 4 + tg];
                afr[mf][3] = sA[mr + 8][kb + 4 + tg];
            }
#pragma unroll
            for (int nf = 0; nf < 4; nf++) {
                int oc = obase + nf * 8 + g;
                bfr[nf][0] = sB[oc][kb + tg];
                bfr[nf][1] = sB[oc][kb + 4 + tg];
            }
#pragma unroll
            for (int mf = 0; mf < 2; mf++)
#pragma unroll
                for (int nf = 0; nf < 4; nf++)
                    mma8(acc[mf][nf], afr[mf], bfr[nf]);
        }
        __syncthreads();
    }
#pragma unroll
    for (int mf = 0; mf < 2; mf++) {
#pragma unroll
        for (int nf = 0; nf < 4; nf++) {
            int c = obase + nf * 8 + 2 * tg;
            int r0 = m0 + mbase + mf * 16 + g;
            int r1 = r0 + 8;
            float b0 = fc2b[c], b1 = fc2b[c + 1];
            float w0 = Wa[c],   w1 = Wa[c + 1];
            float v0 = acc[mf][nf][0] + b0, v1 = acc[mf][nf][1] + b1;
            float v2 = acc[mf][nf][2] + b0, v3 = acc[mf][nf][3] + b1;
            *(float2*)&out[OFF_XPROJ + (long long)r0 * O_ + c] = make_float2(v0, v1);
            *(float2*)&out[OFF_XPROJ + (long long)r1 * O_ + c] = make_float2(v2, v3);
            g_xpwTt[(long long)c       * ROWS + r0] = f2tf(v0 + w0);
            g_xpwTt[(long long)(c + 1) * ROWS + r0] = f2tf(v1 + w1);
            g_xpwTt[(long long)c       * ROWS + r1] = f2tf(v2 + w0);
            g_xpwTt[(long long)(c + 1) * ROWS + r1] = f2tf(v3 + w1);
        }
    }
}

// ---------------------------------------------------------------------------
// K5: logits = x_proj - A1^T @ xpw -- tf32 mma + ldmatrix fragments.
// block: 128m x 64o, 8 warps (4m x 2o). Both operands pre-converted.
// ---------------------------------------------------------------------------
__global__ __launch_bounds__(256) void k5_logits(float* __restrict__ out)
{
    __shared__ unsigned sA[128][36];
    __shared__ unsigned sB[64][36];
    const int b  = blockIdx.x >> 4;
    const int m0 = (blockIdx.x & 15) * 128;
    const int tid = threadIdx.x;
    const int w = tid >> 5, lane = tid & 31;
    const int g = lane >> 2, tg = lane & 3;
    const int mbase = (w >> 1) * 32;
    const int obase = (w & 1) * 32;

    unsigned aBase[2], bBase[2];
#pragma unroll
    for (int mf = 0; mf < 2; mf++)
        aBase[mf] = smem_u32(&sA[mbase + mf * 16 + (lane & 15)][4 * (lane >> 4)]);
#pragma unroll
    for (int p = 0; p < 2; p++)
        bBase[p] = smem_u32(&sB[obase + (2 * p + (lane >> 4)) * 8 + (lane & 7)]
                               [4 * ((lane >> 3) & 1)]);

    float acc[2][4][4];
#pragma unroll
    for (int mf = 0; mf < 2; mf++)
#pragma unroll
        for (int nf = 0; nf < 4; nf++)
#pragma unroll
            for (int t = 0; t < 4; t++) acc[mf][nf][t] = 0.f;

    for (int n0 = 0; n0 < N_; n0 += 32) {
#pragma unroll
        for (int it = 0; it < 4; it++) {            // sA: 128x32 raw copy
            int idx = tid + it * 256;
            int m = idx >> 3, kk4 = idx & 7;
            *(uint4*)&sA[m][kk4 * 4] =
                *(const uint4*)&g_A1T[(long long)(m0 + m) * N_ + n0 + kk4 * 4];
        }
#pragma unroll
        for (int it = 0; it < 2; it++) {            // sB: 64x32 raw copy
            int idx = tid + it * 256;
            int o = idx >> 3, kk4 = idx & 7;
            *(uint4*)&sB[o][kk4 * 4] =
                *(const uint4*)&g_xpwTt[(long long)o * ROWS + b * N_ + n0 + kk4 * 4];
        }
        __syncthreads();

#pragma unroll
        for (int ks = 0; ks < 4; ks++) {
            unsigned afr[2][4], bfr[4][2];
            ldm_x4(afr[0][0], afr[0][1], afr[0][2], afr[0][3], aBase[0] + ks * 32);
            ldm_x4(afr[1][0], afr[1][1], afr[1][2], afr[1][3], aBase[1] + ks * 32);
            ldm_x4(bfr[0][0], bfr[0][1], bfr[1][0], bfr[1][1], bBase[0] + ks * 32);
            ldm_x4(bfr[2][0], bfr[2][1], bfr[3][0], bfr[3][1], bBase[1] + ks * 32);
#pragma unroll
            for (int mf = 0; mf < 2; mf++)
#pragma unroll
                for (int nf = 0; nf < 4; nf++)
                    mma8(acc[mf][nf], afr[mf], bfr[nf]);
        }
        __syncthreads();
    }

#pragma unroll
    for (int mf = 0; mf < 2; mf++) {
#pragma unroll
        for (int nf = 0; nf < 4; nf++) {
            int c = obase + nf * 8 + 2 * tg;
            int r0 = b * N_ + m0 + mbase + mf * 16 + g;
            int r1 = r0 + 8;
            float2 xp0 = *(const float2*)&out[OFF_XPROJ + (long long)r0 * O_ + c];
            float2 xp1 = *(const float2*)&out[OFF_XPROJ + (long long)r1 * O_ + c];
            float2 o0, o1;
            o0.x = xp0.x - acc[mf][nf][0]; o0.y = xp0.y - acc[mf][nf][1];
            o1.x = xp1.x - acc[mf][nf][2]; o1.y = xp1.y - acc[mf][nf][3];
            *(float2*)&out[OFF_LOGITS + (long long)r0 * O_ + c] = o0;
            *(float2*)&out[OFF_LOGITS + (long long)r1 * O_ + c] = o1;
        }
    }
}

// ---------------------------------------------------------------------------
extern "C" void kernel_launch(void* const* d_in, const int* in_sizes, int n_in,
                              void* d_out, int out_size)
{
    const float* x     = (const float*)d_in[0];
    const float* adjA  = (const float*)d_in[1];
    const float* W     = (const float*)d_in[2];
    const float* a_src = (const float*)d_in[3];
    const float* a_dst = (const float*)d_in[4];
    const float* fc2w  = (const float*)d_in[5];
    const float* fc2b  = (const float*)d_in[6];
    const float* Wa    = (const float*)d_in[7];
    const float* z     = (const float*)d_in[8];
    const float* zpos  = (const float*)d_in[9];
    float* out = (float*)d_out;

    k0_misc      <<<(N_ * N_ / 4 + 255) / 256, 256>>>(adjA, zpos, Wa, z, out);
    k0b_transpose<<<64 * 64, 256>>>(out);
    k1_h         <<<ROWS / 64, 256>>>(x, W);
    k1b_e        <<<ROWS / 8, 256>>>(a_src, a_dst);
    k2_stats     <<<N_, 256>>>(adjA);
    k3_attn      <<<B_ * (N_ / 64), 256>>>(adjA);
    k4_xproj     <<<ROWS / 128, 256>>>(fc2w, fc2b, Wa, out);
    k5_logits    <<<B_ * (N_ / 128), 256>>>(out);
}

// round 12
// speedup vs baseline: 2.9271x; 1.1258x over previous
#include <cuda_runtime.h>
#include <math.h>

// Problem constants
constexpr int B_ = 8, N_ = 2048, F_ = 128, H_ = 128, O_ = 64;
constexpr int ROWS = B_ * N_;            // 16384
constexpr float NEG_INF = -1.0e9f;

// Output layout (tuple flattened in order)
constexpr long long OFF_XPROJ  = 0;
constexpr long long OFF_LOGITS = OFF_XPROJ  + (long long)B_ * N_ * O_;
constexpr long long OFF_ADJ1   = OFF_LOGITS + (long long)B_ * N_ * O_;
constexpr long long OFF_EYE    = OFF_ADJ1   + (long long)N_ * N_;
constexpr long long OFF_Z      = OFF_EYE    + (long long)N_ * N_;
constexpr long long OFF_ZPOS   = OFF_Z      + 1;                    // odd -> 4B only
constexpr long long OFF_ADJA   = OFF_ZPOS   + (long long)N_ * N_;   // odd
constexpr long long OFF_WA     = OFF_ADJA   + (long long)N_ * N_;

// Scratch (device globals). *t arrays hold tf32 bit patterns.
__device__ unsigned g_hTt  [H_ * ROWS];   // tf32(h^T)       (B-operand k3)
__device__ float    g_hp   [ROWS * H_];   // elu(attn@h)
__device__ unsigned g_A1T  [N_ * N_];     // tf32(adj_A1^T)  (A-operand k5)
__device__ unsigned g_xpwTt[O_ * ROWS];   // tf32((xp+Wa)^T) (B-operand k5)
__device__ float    g_es   [ROWS];
__device__ float    g_ed   [ROWS];
__device__ float    g_mx   [ROWS];
__device__ float    g_rs   [ROWS];

// ---- helpers --------------------------------------------------------------
__device__ __forceinline__ unsigned f2tf(float f) {
    unsigned u; asm("cvt.rna.tf32.f32 %0, %1;" : "=r"(u) : "f"(f)); return u;
}
__device__ __forceinline__ void mma8(float* d, const unsigned* a, const unsigned* b) {
    asm volatile("mma.sync.aligned.m16n8k8.row.col.f32.tf32.tf32.f32 "
        "{%0,%1,%2,%3},{%4,%5,%6,%7},{%8,%9},{%0,%1,%2,%3};"
        : "+f"(d[0]), "+f"(d[1]), "+f"(d[2]), "+f"(d[3])
        : "r"(a[0]), "r"(a[1]), "r"(a[2]), "r"(a[3]), "r"(b[0]), "r"(b[1]));
}
__device__ __forceinline__ unsigned smem_u32(const void* p) {
    return (unsigned)__cvta_generic_to_shared(p);
}
__device__ __forceinline__ void ldm_x4(unsigned& r0, unsigned& r1,
                                       unsigned& r2, unsigned& r3, unsigned addr) {
    asm volatile("ldmatrix.sync.aligned.m8n8.x4.shared.b16 {%0,%1,%2,%3}, [%4];"
        : "=r"(r0), "=r"(r1), "=r"(r2), "=r"(r3) : "r"(addr));
}
__device__ __forceinline__ void cp16(unsigned dst, const void* src) {
    asm volatile("cp.async.cg.shared.global [%0], [%1], 16;" :: "r"(dst), "l"(src));
}
#define CP_COMMIT() asm volatile("cp.async.commit_group;")
#define CP_WAIT1()  asm volatile("cp.async.wait_group 1;" ::: "memory")

// ---------------------------------------------------------------------------
// K0: elementwise outputs (adj_A1, eye, copies)
// ---------------------------------------------------------------------------
__global__ void k0_misc(const float* __restrict__ adjA,
                        const float* __restrict__ zpos,
                        const float* __restrict__ Wa,
                        const float* __restrict__ z,
                        float* __restrict__ out)
{
    int i4 = blockIdx.x * blockDim.x + threadIdx.x;
    if (i4 < (N_ * N_ / 4)) {
        float4 a4  = ((const float4*)adjA)[i4];
        float4 zp4 = ((const float4*)zpos)[i4];
        int g = i4 * 4;
        float* adja_dst = out + OFF_ADJA + g;
        float* zpos_dst = out + OFF_ZPOS + g;
        const float* ap = (const float*)&a4;
        const float* zp = (const float*)&zp4;
#pragma unroll
        for (int l = 0; l < 4; l++) { adja_dst[l] = ap[l]; zpos_dst[l] = zp[l]; }

        float4 s4; float* sp = (float*)&s4;
#pragma unroll
        for (int l = 0; l < 4; l++) {
            float c = fminf(fmaxf(ap[l], -3.f), 3.f);
            float s = sinhf(3.f * c);
            sp[l] = fminf(fmaxf(s, -1000.f), 1000.f);
        }
        ((float4*)(out + OFF_ADJ1))[i4] = s4;

        int row = g >> 11, col = g & 2047;
        float4 e4; float* ep = (float*)&e4;
#pragma unroll
        for (int l = 0; l < 4; l++) ep[l] = (col + l == row) ? 1.f : 0.f;
        ((float4*)(out + OFF_EYE))[i4] = e4;
    }
    if (blockIdx.x == 0) {
        if (threadIdx.x < O_)  out[OFF_WA + threadIdx.x] = Wa[threadIdx.x];
        if (threadIdx.x == O_) out[OFF_Z] = z[0];
    }
}

// ---------------------------------------------------------------------------
// K0b: g_A1T = tf32(adj_A1^T)  (32x32 smem tiles)
// ---------------------------------------------------------------------------
__global__ __launch_bounds__(256) void k0b_transpose(const float* __restrict__ out)
{
    __shared__ float t[32][33];
    const float* A1 = out + OFF_ADJ1;
    int bx = blockIdx.x;
    int c0 = (bx & 63) * 32;
    int r0 = (bx >> 6) * 32;
    int tid = threadIdx.x;
    int lr = tid >> 5, lc = tid & 31;
#pragma unroll
    for (int it = 0; it < 4; it++) {
        int row = lr + it * 8;
        t[row][lc] = A1[(long long)(r0 + row) * N_ + c0 + lc];
    }
    __syncthreads();
#pragma unroll
    for (int it = 0; it < 4; it++) {
        int row = lr + it * 8;
        g_A1T[(long long)(c0 + row) * N_ + r0 + lc] = f2tf(t[lc][row]);
    }
}

// ---------------------------------------------------------------------------
// K1: h = x @ W^T -- tf32 mma + fused e_src/e_dst reduction (was k1b).
// block 64m x 128h, 8 warps (2m x 4h). Writes g_hTt, g_es, g_ed.
// ---------------------------------------------------------------------------
__global__ __launch_bounds__(256) void k1_h(const float* __restrict__ x,
                                            const float* __restrict__ W,
                                            const float* __restrict__ a_src,
                                            const float* __restrict__ a_dst)
{
    __shared__ unsigned sA[64][36];
    __shared__ unsigned sB[128][36];
    __shared__ float eps[4][64], epd[4][64];
    const int m0 = blockIdx.x * 64;
    const int tid = threadIdx.x;
    const int w = tid >> 5, lane = tid & 31;
    const int g = lane >> 2, tg = lane & 3;
    const int mbase = (w >> 2) * 32;
    const int hbase = (w & 3) * 32;
    const int hw = w & 3;

    float acc[2][4][4];
#pragma unroll
    for (int mf = 0; mf < 2; mf++)
#pragma unroll
        for (int nf = 0; nf < 4; nf++)
#pragma unroll
            for (int t = 0; t < 4; t++) acc[mf][nf][t] = 0.f;

    for (int f0 = 0; f0 < F_; f0 += 32) {
#pragma unroll
        for (int it = 0; it < 2; it++) {            // sA: 64x32
            int idx = tid + it * 256;
            int mi = idx >> 3, k4 = idx & 7;
            float4 v = *(const float4*)&x[(m0 + mi) * F_ + f0 + k4 * 4];
            uint4 u = { f2tf(v.x), f2tf(v.y), f2tf(v.z), f2tf(v.w) };
            *(uint4*)&sA[mi][k4 * 4] = u;
        }
#pragma unroll
        for (int it = 0; it < 4; it++) {            // sB: 128x32
            int idx = tid + it * 256;
            int hh = idx >> 3, k4 = idx & 7;
            float4 v = *(const float4*)&W[hh * F_ + f0 + k4 * 4];
            uint4 u = { f2tf(v.x), f2tf(v.y), f2tf(v.z), f2tf(v.w) };
            *(uint4*)&sB[hh][k4 * 4] = u;
        }
        __syncthreads();
#pragma unroll
        for (int ks = 0; ks < 4; ks++) {
            int kb = ks * 8;
            unsigned afr[2][4], bfr[4][2];
#pragma unroll
            for (int mf = 0; mf < 2; mf++) {
                int mr = mbase + mf * 16 + g;
                afr[mf][0] = sA[mr    ][kb + tg];
                afr[mf][1] = sA[mr + 8][kb + tg];
                afr[mf][2] = sA[mr    ][kb + 4 + tg];
                afr[mf][3] = sA[mr + 8][kb + 4 + tg];
            }
#pragma unroll
            for (int nf = 0; nf < 4; nf++) {
                int cc = hbase + nf * 8 + g;
                bfr[nf][0] = sB[cc][kb + tg];
                bfr[nf][1] = sB[cc][kb + 4 + tg];
            }
#pragma unroll
            for (int mf = 0; mf < 2; mf++)
#pragma unroll
                for (int nf = 0; nf < 4; nf++)
                    mma8(acc[mf][nf], afr[mf], bfr[nf]);
        }
        __syncthreads();
    }

    // epilogue: g_hTt stores + per-thread e partials
    float ps[4] = {0.f, 0.f, 0.f, 0.f};   // slot = mf*2 + (0:r0, 1:r1)
    float pd[4] = {0.f, 0.f, 0.f, 0.f};
#pragma unroll
    for (int mf = 0; mf < 2; mf++) {
#pragma unroll
        for (int nf = 0; nf < 4; nf++) {
            int c = hbase + nf * 8 + 2 * tg;
            int r0 = m0 + mbase + mf * 16 + g;
            int r1 = r0 + 8;
            float v0 = acc[mf][nf][0], v1 = acc[mf][nf][1];
            float v2 = acc[mf][nf][2], v3 = acc[mf][nf][3];
            g_hTt[(long long)c       * ROWS + r0] = f2tf(v0);
            g_hTt[(long long)(c + 1) * ROWS + r0] = f2tf(v1);
            g_hTt[(long long)c       * ROWS + r1] = f2tf(v2);
            g_hTt[(long long)(c + 1) * ROWS + r1] = f2tf(v3);
            float as0 = a_src[c], as1 = a_src[c + 1];
            float ad0 = a_dst[c], ad1 = a_dst[c + 1];
            ps[mf * 2 + 0] += v0 * as0 + v1 * as1;
            ps[mf * 2 + 1] += v2 * as0 + v3 * as1;
            pd[mf * 2 + 0] += v0 * ad0 + v1 * ad1;
            pd[mf * 2 + 1] += v2 * ad0 + v3 * ad1;
        }
    }
    // reduce over tg (4 lanes)
#pragma unroll
    for (int off = 1; off <= 2; off <<= 1) {
#pragma unroll
        for (int s = 0; s < 4; s++) {
            ps[s] += __shfl_xor_sync(0xffffffffu, ps[s], off);
            pd[s] += __shfl_xor_sync(0xffffffffu, pd[s], off);
        }
    }
    if (tg == 0) {
#pragma unroll
        for (int s = 0; s < 4; s++) {
            int row = mbase + (s >> 1) * 16 + g + (s & 1) * 8;
            eps[hw][row] = ps[s];
            epd[hw][row] = pd[s];
        }
    }
    __syncthreads();
    if (tid < 64) {
        float s = eps[0][tid] + eps[1][tid] + eps[2][tid] + eps[3][tid];
        float d = epd[0][tid] + epd[1][tid] + epd[2][tid] + epd[3][tid];
        g_es[m0 + tid] = s;
        g_ed[m0 + tid] = d;
    }
}

// ---------------------------------------------------------------------------
// K2: softmax row stats (mask shared across batches, scores reg-cached)
// ---------------------------------------------------------------------------
__global__ __launch_bounds__(256) void k2_stats(const float* __restrict__ adjA)
{
    __shared__ unsigned char msk[N_];
    const int m = blockIdx.x;
    const int tid = threadIdx.x;
    const int warp = tid >> 5, lane = tid & 31;
#pragma unroll
    for (int it = 0; it < 8; it++) {
        int n = tid + it * 256;
        float adj = adjA[(long long)m * N_ + n] + (n == m ? 1.f : 0.f);
        msk[n] = (adj <= 0.f) ? 1 : 0;
    }
    __syncthreads();

    const int b = warp;
    const int r = b * N_ + m;
    const float es = g_es[r];
    const float* edb = g_ed + b * N_;

    float sc[64];
    float mx = -INFINITY;
#pragma unroll
    for (int t = 0; t < 64; t++) {
        int n = lane + 32 * t;
        float v = es + edb[n];
        float lr = fmaxf(v, 0.2f * v);
        float s = msk[n] ? NEG_INF : lr;
        sc[t] = s;
        mx = fmaxf(mx, s);
    }
#pragma unroll
    for (int off = 16; off >= 1; off >>= 1)
        mx = fmaxf(mx, __shfl_xor_sync(0xffffffffu, mx, off));

    float sm = 0.f;
#pragma unroll
    for (int t = 0; t < 64; t++) sm += __expf(sc[t] - mx);
#pragma unroll
    for (int off = 16; off >= 1; off >>= 1)
        sm += __shfl_xor_sync(0xffffffffu, sm, off);

    if (lane == 0) { g_mx[r] = mx; g_rs[r] = 1.f / sm; }
}

// ---------------------------------------------------------------------------
// K3: h_prime = elu(attn @ h) -- tf32 mma + ldmatrix + cp.async pipeline.
// dynamic smem: w_s[2][64][36] | sB[3][128][36] | s_mx/s_rs/s_es[64]
// 3-stage sB ring, depth-1 prefetch, 1 __syncthreads per K-iter.
// ---------------------------------------------------------------------------
constexpr int K3_WWORDS = 64 * 36;            // 2304
constexpr int K3_BWORDS = 128 * 36;           // 4608
constexpr int K3_SMEM   = (2 * K3_WWORDS + 3 * K3_BWORDS + 3 * 64) * 4;  // 74496 B

__global__ __launch_bounds__(256) void k3_attn(const float* __restrict__ adjA)
{
    extern __shared__ unsigned dyn3[];
    unsigned* w_s = dyn3;                       // 2 bufs
    unsigned* sBp = dyn3 + 2 * K3_WWORDS;       // 3 stages
    float* s_mx = (float*)(dyn3 + 2 * K3_WWORDS + 3 * K3_BWORDS);
    float* s_rs = s_mx + 64;
    float* s_es = s_rs + 64;

    const int b  = blockIdx.x >> 5;
    const int m0 = (blockIdx.x & 31) * 64;
    const int rbase = b * N_ + m0;
    const int tid = threadIdx.x;
    const int w = tid >> 5, lane = tid & 31;
    const int g = lane >> 2, tg = lane & 3;
    const int mbase = (w >> 2) * 32;
    const int hbase = (w & 3) * 32;
    const long long bN = (long long)b * N_;

    if (tid < 64) {
        s_mx[tid] = g_mx[rbase + tid];
        s_rs[tid] = g_rs[rbase + tid];
        s_es[tid] = g_es[rbase + tid];
    }

    // per-thread cp.async targets (4 per tile)
    const int pc  = tid >> 3;            // 0..31 row group? (idx>>3 for it=0)
    // ldmatrix base addresses (buffer/stage 0)
    unsigned aBase[2], bBase[2];
#pragma unroll
    for (int mf = 0; mf < 2; mf++)
        aBase[mf] = smem_u32(w_s + (mbase + mf * 16 + (lane & 15)) * 36 + 4 * (lane >> 4));
#pragma unroll
    for (int p = 0; p < 2; p++)
        bBase[p] = smem_u32(sBp + (hbase + (2 * p + (lane >> 4)) * 8 + (lane & 7)) * 36
                                + 4 * ((lane >> 3) & 1));

    // prefetch tile 0 into stage 0
    {
#pragma unroll
        for (int it = 0; it < 4; it++) {
            int idx = tid + it * 256;
            int c = idx >> 3, kk4 = idx & 7;
            cp16(smem_u32(sBp + c * 36 + kk4 * 4),
                 &g_hTt[(long long)c * ROWS + bN + kk4 * 4]);
        }
        CP_COMMIT();
    }
    __syncthreads();   // s_mx/s_es visible

    float acc[2][4][4];
#pragma unroll
    for (int mf = 0; mf < 2; mf++)
#pragma unroll
        for (int nf = 0; nf < 4; nf++)
#pragma unroll
            for (int t = 0; t < 4; t++) acc[mf][nf][t] = 0.f;

    const int mi = tid >> 2;
    const int nb = (tid & 3) * 8;
    const int gm = m0 + mi;
    const float* arow = adjA + (long long)gm * N_;
    const float* edb  = g_ed + bN;
    const float es = s_es[mi], mxv = s_mx[mi], rs = s_rs[mi];

    for (int it = 0; it < 64; it++) {
        const int n0 = it * 32;
        const int wbuf = (it & 1) * K3_WWORDS;
        // attn weights for this 64x32 tile -> w_s[it&1]
        {
            float4 a4[2], e4[2];
            a4[0] = *(const float4*)(arow + n0 + nb);
            a4[1] = *(const float4*)(arow + n0 + nb + 4);
            e4[0] = *(const float4*)(edb  + n0 + nb);
            e4[1] = *(const float4*)(edb  + n0 + nb + 4);
            const float* ap = (const float*)a4;
            const float* ep = (const float*)e4;
#pragma unroll
            for (int jj = 0; jj < 8; jj++) {
                int n = n0 + nb + jj;
                float adj = ap[jj] + (n == gm ? 1.f : 0.f);
                float t = es + ep[jj];
                float lr = fmaxf(t, 0.2f * t);
                float sc = (adj <= 0.f) ? NEG_INF : lr;
                w_s[wbuf + mi * 36 + nb + jj] = f2tf(__expf(sc - mxv) * rs);
            }
        }
        // prefetch tile it+1 into stage (it+1)%3
        if (it + 1 < 64) {
            const int st = ((it + 1) % 3) * K3_BWORDS;
            const long long gbase = bN + (long long)(it + 1) * 32;
#pragma unroll
            for (int c4 = 0; c4 < 4; c4++) {
                int idx = tid + c4 * 256;
                int c = idx >> 3, kk4 = idx & 7;
                cp16(smem_u32(sBp + st + c * 36 + kk4 * 4),
                     &g_hTt[(long long)c * ROWS + gbase + kk4 * 4]);
            }
        }
        CP_COMMIT();
        CP_WAIT1();          // stage it%3 complete
        __syncthreads();     // weights + tile visible to all warps

        const unsigned aOff = (unsigned)(it & 1) * (K3_WWORDS * 4);
        const unsigned bOff = (unsigned)(it % 3) * (K3_BWORDS * 4);
#pragma unroll
        for (int ks = 0; ks < 4; ks++) {
            unsigned afr[2][4], bfr[4][2];
            ldm_x4(afr[0][0], afr[0][1], afr[0][2], afr[0][3], aBase[0] + aOff + ks * 32);
            ldm_x4(afr[1][0], afr[1][1], afr[1][2], afr[1][3], aBase[1] + aOff + ks * 32);
            ldm_x4(bfr[0][0], bfr[0][1], bfr[1][0], bfr[1][1], bBase[0] + bOff + ks * 32);
            ldm_x4(bfr[2][0], bfr[2][1], bfr[3][0], bfr[3][1], bBase[1] + bOff + ks * 32);
#pragma unroll
            for (int mf = 0; mf < 2; mf++)
#pragma unroll
                for (int nf = 0; nf < 4; nf++)
                    mma8(acc[mf][nf], afr[mf], bfr[nf]);
        }
        // no trailing sync: next write to this sB stage is 3 iters away
        // (barriers at it+1, it+2 intervene); w_s buffer reused at it+2
        // (barrier at it+1 intervenes).
    }

#pragma unroll
    for (int mf = 0; mf < 2; mf++) {
#pragma unroll
        for (int nf = 0; nf < 4; nf++) {
            int c = hbase + nf * 8 + 2 * tg;
            int r0 = rbase + mbase + mf * 16 + g;
            int r1 = r0 + 8;
            float2 lo, hi;
            float v0 = acc[mf][nf][0], v1 = acc[mf][nf][1];
            float v2 = acc[mf][nf][2], v3 = acc[mf][nf][3];
            lo.x = v0 > 0.f ? v0 : expm1f(v0);
            lo.y = v1 > 0.f ? v1 : expm1f(v1);
            hi.x = v2 > 0.f ? v2 : expm1f(v2);
            hi.y = v3 > 0.f ? v3 : expm1f(v3);
            *(float2*)&g_hp[r0 * H_ + c] = lo;
            *(float2*)&g_hp[r1 * H_ + c] = hi;
        }
    }
}

// ---------------------------------------------------------------------------
// K4: x_proj = hp @ fc2_w^T + fc2_b -- tf32 mma. block 128m x 64o.
// ---------------------------------------------------------------------------
__global__ __launch_bounds__(256) void k4_xproj(const float* __restrict__ fc2w,
                                                const float* __restrict__ fc2b,
                                                const float* __restrict__ Wa,
                                                float* __restrict__ out)
{
    __shared__ unsigned sA[128][36];
    __shared__ unsigned sB[64][36];
    const int m0 = blockIdx.x * 128;
    const int tid = threadIdx.x;
    const int w = tid >> 5, lane = tid & 31;
    const int g = lane >> 2, tg = lane & 3;
    const int mbase = (w >> 1) * 32;
    const int obase = (w & 1) * 32;

    float acc[2][4][4];
#pragma unroll
    for (int mf = 0; mf < 2; mf++)
#pragma unroll
        for (int nf = 0; nf < 4; nf++)
#pragma unroll
            for (int t = 0; t < 4; t++) acc[mf][nf][t] = 0.f;

    for (int f0 = 0; f0 < H_; f0 += 32) {
#pragma unroll
        for (int it = 0; it < 4; it++) {            // sA: 128x32
            int idx = tid + it * 256;
            int mi = idx >> 3, k4 = idx & 7;
            float4 v = *(const float4*)&g_hp[(m0 + mi) * H_ + f0 + k4 * 4];
            uint4 u = { f2tf(v.x), f2tf(v.y), f2tf(v.z), f2tf(v.w) };
            *(uint4*)&sA[mi][k4 * 4] = u;
        }
#pragma unroll
        for (int it = 0; it < 2; it++) {            // sB: 64x32
            int idx = tid + it * 256;
            int o = idx >> 3, k4 = idx & 7;
            float4 v = *(const float4*)&fc2w[o * H_ + f0 + k4 * 4];
            uint4 u = { f2tf(v.x), f2tf(v.y), f2tf(v.z), f2tf(v.w) };
            *(uint4*)&sB[o][k4 * 4] = u;
        }
        __syncthreads();
#pragma unroll
        for (int ks = 0; ks < 4; ks++) {
            int kb = ks * 8;
            unsigned afr[2][4], bfr[4][2];
#pragma unroll
            for (int mf = 0; mf < 2; mf++) {
                int mr = mbase + mf * 16 + g;
                afr[mf][0] = sA[mr    ][kb + tg];
                afr[mf][1] = sA[mr + 8][kb + tg];
                afr[mf][2] = sA[mr    ][kb + 4 + tg];
                afr[mf][3] = sA[mr + 8][kb + 4 + tg];
            }
#pragma unroll
            for (int nf = 0; nf < 4; nf++) {
                int oc = obase + nf * 8 + g;
                bfr[nf][0] = sB[oc][kb + tg];
                bfr[nf][1] = sB[oc][kb + 4 + tg];
            }
#pragma unroll
            for (int mf = 0; mf < 2; mf++)
#pragma unroll
                for (int nf = 0; nf < 4; nf++)
                    mma8(acc[mf][nf], afr[mf], bfr[nf]);
        }
        __syncthreads();
    }
#pragma unroll
    for (int mf = 0; mf < 2; mf++) {
#pragma unroll
        for (int nf = 0; nf < 4; nf++) {
            int c = obase + nf * 8 + 2 * tg;
            int r0 = m0 + mbase + mf * 16 + g;
            int r1 = r0 + 8;
            float b0 = fc2b[c], b1 = fc2b[c + 1];
            float w0 = Wa[c],   w1 = Wa[c + 1];
            float v0 = acc[mf][nf][0] + b0, v1 = acc[mf][nf][1] + b1;
            float v2 = acc[mf][nf][2] + b0, v3 = acc[mf][nf][3] + b1;
            *(float2*)&out[OFF_XPROJ + (long long)r0 * O_ + c] = make_float2(v0, v1);
            *(float2*)&out[OFF_XPROJ + (long long)r1 * O_ + c] = make_float2(v2, v3);
            g_xpwTt[(long long)c       * ROWS + r0] = f2tf(v0 + w0);
            g_xpwTt[(long long)(c + 1) * ROWS + r0] = f2tf(v1 + w1);
            g_xpwTt[(long long)c       * ROWS + r1] = f2tf(v2 + w0);
            g_xpwTt[(long long)(c + 1) * ROWS + r1] = f2tf(v3 + w1);
        }
    }
}

// ---------------------------------------------------------------------------
// K5: logits = x_proj - A1^T @ xpw -- tf32 mma + ldmatrix + cp.async.
// dynamic smem: sA[3][128][36] | sB[3][64][36]. 1 sync/iter.
// ---------------------------------------------------------------------------
constexpr int K5_AWORDS = 128 * 36;           // 4608
constexpr int K5_BWORDS = 64 * 36;            // 2304
constexpr int K5_SMEM   = (3 * K5_AWORDS + 3 * K5_BWORDS) * 4;   // 82944 B

__global__ __launch_bounds__(256) void k5_logits(float* __restrict__ out)
{
    extern __shared__ unsigned dyn5[];
    unsigned* sAp = dyn5;
    unsigned* sBp = dyn5 + 3 * K5_AWORDS;

    const int b  = blockIdx.x >> 4;
    const int m0 = (blockIdx.x & 15) * 128;
    const int tid = threadIdx.x;
    const int w = tid >> 5, lane = tid & 31;
    const int g = lane >> 2, tg = lane & 3;
    const int mbase = (w >> 1) * 32;
    const int obase = (w & 1) * 32;
    const long long bN = (long long)b * N_;

    unsigned aBase[2], bBase[2];
#pragma unroll
    for (int mf = 0; mf < 2; mf++)
        aBase[mf] = smem_u32(sAp + (mbase + mf * 16 + (lane & 15)) * 36 + 4 * (lane >> 4));
#pragma unroll
    for (int p = 0; p < 2; p++)
        bBase[p] = smem_u32(sBp + (obase + (2 * p + (lane >> 4)) * 8 + (lane & 7)) * 36
                                + 4 * ((lane >> 3) & 1));

    // prefetch tile 0
    {
#pragma unroll
        for (int c4 = 0; c4 < 4; c4++) {
            int idx = tid + c4 * 256;
            int m = idx >> 3, kk4 = idx & 7;
            cp16(smem_u32(sAp + m * 36 + kk4 * 4),
                 &g_A1T[(long long)(m0 + m) * N_ + kk4 * 4]);
        }
#pragma unroll
        for (int c4 = 0; c4 < 2; c4++) {
            int idx = tid + c4 * 256;
            int o = idx >> 3, kk4 = idx & 7;
            cp16(smem_u32(sBp + o * 36 + kk4 * 4),
                 &g_xpwTt[(long long)o * ROWS + bN + kk4 * 4]);
        }
        CP_COMMIT();
    }

    float acc[2][4][4];
#pragma unroll
    for (int mf = 0; mf < 2; mf++)
#pragma unroll
        for (int nf = 0; nf < 4; nf++)
#pragma unroll
            for (int t = 0; t < 4; t++) acc[mf][nf][t] = 0.f;

    for (int it = 0; it < 64; it++) {
        if (it + 1 < 64) {
            const int stA = ((it + 1) % 3) * K5_AWORDS;
            const int stB = ((it + 1) % 3) * K5_BWORDS;
            const int n1 = (it + 1) * 32;
#pragma unroll
            for (int c4 = 0; c4 < 4; c4++) {
                int idx = tid + c4 * 256;
                int m = idx >> 3, kk4 = idx & 7;
                cp16(smem_u32(sAp + stA + m * 36 + kk4 * 4),
                     &g_A1T[(long long)(m0 + m) * N_ + n1 + kk4 * 4]);
            }
#pragma unroll
            for (int c4 = 0; c4 < 2; c4++) {
                int idx = tid + c4 * 256;
                int o = idx >> 3, kk4 = idx & 7;
                cp16(smem_u32(sBp + stB + o * 36 + kk4 * 4),
                     &g_xpwTt[(long long)o * ROWS + bN + n1 + kk4 * 4]);
            }
        }
        CP_COMMIT();
        CP_WAIT1();
        __syncthreads();

        const unsigned aOff = (unsigned)(it % 3) * (K5_AWORDS * 4);
        const unsigned bOff = (unsigned)(it % 3) * (K5_BWORDS * 4);
#pragma unroll
        for (int ks = 0; ks < 4; ks++) {
            unsigned afr[2][4], bfr[4][2];
            ldm_x4(afr[0][0], afr[0][1], afr[0][2], afr[0][3], aBase[0] + aOff + ks * 32);
            ldm_x4(afr[1][0], afr[1][1], afr[1][2], afr[1][3], aBase[1] + aOff + ks * 32);
            ldm_x4(bfr[0][0], bfr[0][1], bfr[1][0], bfr[1][1], bBase[0] + bOff + ks * 32);
            ldm_x4(bfr[2][0], bfr[2][1], bfr[3][0], bfr[3][1], bBase[1] + bOff + ks * 32);
#pragma unroll
            for (int mf = 0; mf < 2; mf++)
#pragma unroll
                for (int nf = 0; nf < 4; nf++)
                    mma8(acc[mf][nf], afr[mf], bfr[nf]);
        }
    }

#pragma unroll
    for (int mf = 0; mf < 2; mf++) {
#pragma unroll
        for (int nf = 0; nf < 4; nf++) {
            int c = obase + nf * 8 + 2 * tg;
            int r0 = b * N_ + m0 + mbase + mf * 16 + g;
            int r1 = r0 + 8;
            float2 xp0 = *(const float2*)&out[OFF_XPROJ + (long long)r0 * O_ + c];
            float2 xp1 = *(const float2*)&out[OFF_XPROJ + (long long)r1 * O_ + c];
            float2 o0, o1;
            o0.x = xp0.x - acc[mf][nf][0]; o0.y = xp0.y - acc[mf][nf][1];
            o1.x = xp1.x - acc[mf][nf][2]; o1.y = xp1.y - acc[mf][nf][3];
            *(float2*)&out[OFF_LOGITS + (long long)r0 * O_ + c] = o0;
            *(float2*)&out[OFF_LOGITS + (long long)r1 * O_ + c] = o1;
        }
    }
}

// ---------------------------------------------------------------------------
extern "C" void kernel_launch(void* const* d_in, const int* in_sizes, int n_in,
                              void* d_out, int out_size)
{
    const float* x     = (const float*)d_in[0];
    const float* adjA  = (const float*)d_in[1];
    const float* W     = (const float*)d_in[2];
    const float* a_src = (const float*)d_in[3];
    const float* a_dst = (const float*)d_in[4];
    const float* fc2w  = (const float*)d_in[5];
    const float* fc2b  = (const float*)d_in[6];
    const float* Wa    = (const float*)d_in[7];
    const float* z     = (const float*)d_in[8];
    const float* zpos  = (const float*)d_in[9];
    float* out = (float*)d_out;

    cudaFuncSetAttribute(k3_attn,  cudaFuncAttributeMaxDynamicSharedMemorySize, K3_SMEM);
    cudaFuncSetAttribute(k5_logits, cudaFuncAttributeMaxDynamicSharedMemorySize, K5_SMEM);

    k0_misc      <<<(N_ * N_ / 4 + 255) / 256, 256>>>(adjA, zpos, Wa, z, out);
    k0b_transpose<<<64 * 64, 256>>>(out);
    k1_h         <<<ROWS / 64, 256>>>(x, W, a_src, a_dst);
    k2_stats     <<<N_, 256>>>(adjA);
    k3_attn      <<<B_ * (N_ / 64), 256, K3_SMEM>>>(adjA);
    k4_xproj     <<<ROWS / 128, 256>>>(fc2w, fc2b, Wa, out);
    k5_logits    <<<B_ * (N_ / 128), 256, K5_SMEM>>>(out);
}

// round 13
// speedup vs baseline: 3.0106x; 1.0285x over previous
#include <cuda_runtime.h>
#include <math.h>

// Problem constants
constexpr int B_ = 8, N_ = 2048, F_ = 128, H_ = 128, O_ = 64;
constexpr int ROWS = B_ * N_;            // 16384
constexpr float NEG_INF = -1.0e9f;

// Output layout (tuple flattened in order)
constexpr long long OFF_XPROJ  = 0;
constexpr long long OFF_LOGITS = OFF_XPROJ  + (long long)B_ * N_ * O_;
constexpr long long OFF_ADJ1   = OFF_LOGITS + (long long)B_ * N_ * O_;
constexpr long long OFF_EYE    = OFF_ADJ1   + (long long)N_ * N_;
constexpr long long OFF_Z      = OFF_EYE    + (long long)N_ * N_;
constexpr long long OFF_ZPOS   = OFF_Z      + 1;                    // odd -> 4B only
constexpr long long OFF_ADJA   = OFF_ZPOS   + (long long)N_ * N_;   // odd
constexpr long long OFF_WA     = OFF_ADJA   + (long long)N_ * N_;

// Scratch (device globals). *t arrays hold tf32 bit patterns.
__device__ unsigned g_hTt  [H_ * ROWS];   // tf32(h^T)       (B-operand k3)
__device__ unsigned g_A1T  [N_ * N_];     // tf32(adj_A1^T)  (A-operand k5)
__device__ unsigned g_xpwTt[O_ * ROWS];   // tf32((xp+Wa)^T) (B-operand k5)
__device__ float    g_es   [ROWS];
__device__ float    g_ed   [ROWS];
__device__ float    g_mx   [ROWS];
__device__ float    g_rs   [ROWS];

// ---- helpers --------------------------------------------------------------
__device__ __forceinline__ unsigned f2tf(float f) {
    unsigned u; asm("cvt.rna.tf32.f32 %0, %1;" : "=r"(u) : "f"(f)); return u;
}
__device__ __forceinline__ void mma8(float* d, const unsigned* a, const unsigned* b) {
    asm volatile("mma.sync.aligned.m16n8k8.row.col.f32.tf32.tf32.f32 "
        "{%0,%1,%2,%3},{%4,%5,%6,%7},{%8,%9},{%0,%1,%2,%3};"
        : "+f"(d[0]), "+f"(d[1]), "+f"(d[2]), "+f"(d[3])
        : "r"(a[0]), "r"(a[1]), "r"(a[2]), "r"(a[3]), "r"(b[0]), "r"(b[1]));
}
__device__ __forceinline__ unsigned smem_u32(const void* p) {
    return (unsigned)__cvta_generic_to_shared(p);
}
__device__ __forceinline__ void ldm_x4(unsigned& r0, unsigned& r1,
                                       unsigned& r2, unsigned& r3, unsigned addr) {
    asm volatile("ldmatrix.sync.aligned.m8n8.x4.shared.b16 {%0,%1,%2,%3}, [%4];"
        : "=r"(r0), "=r"(r1), "=r"(r2), "=r"(r3) : "r"(addr));
}
__device__ __forceinline__ void cp16(unsigned dst, const void* src) {
    asm volatile("cp.async.cg.shared.global [%0], [%1], 16;" :: "r"(dst), "l"(src));
}
#define CP_COMMIT() asm volatile("cp.async.commit_group;")
#define CP_WAIT1()  asm volatile("cp.async.wait_group 1;" ::: "memory")

// ---------------------------------------------------------------------------
// K0: elementwise outputs (adj_A1, eye, copies)
// ---------------------------------------------------------------------------
__global__ void k0_misc(const float* __restrict__ adjA,
                        const float* __restrict__ zpos,
                        const float* __restrict__ Wa,
                        const float* __restrict__ z,
                        float* __restrict__ out)
{
    int i4 = blockIdx.x * blockDim.x + threadIdx.x;
    if (i4 < (N_ * N_ / 4)) {
        float4 a4  = ((const float4*)adjA)[i4];
        float4 zp4 = ((const float4*)zpos)[i4];
        int g = i4 * 4;
        float* adja_dst = out + OFF_ADJA + g;
        float* zpos_dst = out + OFF_ZPOS + g;
        const float* ap = (const float*)&a4;
        const float* zp = (const float*)&zp4;
#pragma unroll
        for (int l = 0; l < 4; l++) { adja_dst[l] = ap[l]; zpos_dst[l] = zp[l]; }

        float4 s4; float* sp = (float*)&s4;
#pragma unroll
        for (int l = 0; l < 4; l++) {
            float c = fminf(fmaxf(ap[l], -3.f), 3.f);
            float s = sinhf(3.f * c);
            sp[l] = fminf(fmaxf(s, -1000.f), 1000.f);
        }
        ((float4*)(out + OFF_ADJ1))[i4] = s4;

        int row = g >> 11, col = g & 2047;
        float4 e4; float* ep = (float*)&e4;
#pragma unroll
        for (int l = 0; l < 4; l++) ep[l] = (col + l == row) ? 1.f : 0.f;
        ((float4*)(out + OFF_EYE))[i4] = e4;
    }
    if (blockIdx.x == 0) {
        if (threadIdx.x < O_)  out[OFF_WA + threadIdx.x] = Wa[threadIdx.x];
        if (threadIdx.x == O_) out[OFF_Z] = z[0];
    }
}

// ---------------------------------------------------------------------------
// K0b: g_A1T = tf32(adj_A1^T)  (32x32 smem tiles)
// ---------------------------------------------------------------------------
__global__ __launch_bounds__(256) void k0b_transpose(const float* __restrict__ out)
{
    __shared__ float t[32][33];
    const float* A1 = out + OFF_ADJ1;
    int bx = blockIdx.x;
    int c0 = (bx & 63) * 32;
    int r0 = (bx >> 6) * 32;
    int tid = threadIdx.x;
    int lr = tid >> 5, lc = tid & 31;
#pragma unroll
    for (int it = 0; it < 4; it++) {
        int row = lr + it * 8;
        t[row][lc] = A1[(long long)(r0 + row) * N_ + c0 + lc];
    }
    __syncthreads();
#pragma unroll
    for (int it = 0; it < 4; it++) {
        int row = lr + it * 8;
        g_A1T[(long long)(c0 + row) * N_ + r0 + lc] = f2tf(t[lc][row]);
    }
}

// ---------------------------------------------------------------------------
// K1: h = x @ W^T -- tf32 mma + fused e_src/e_dst reduction.
// block 64m x 128h, 8 warps (2m x 4h). Writes g_hTt, g_es, g_ed.
// ---------------------------------------------------------------------------
__global__ __launch_bounds__(256) void k1_h(const float* __restrict__ x,
                                            const float* __restrict__ W,
                                            const float* __restrict__ a_src,
                                            const float* __restrict__ a_dst)
{
    __shared__ unsigned sA[64][36];
    __shared__ unsigned sB[128][36];
    __shared__ float eps[4][64], epd[4][64];
    const int m0 = blockIdx.x * 64;
    const int tid = threadIdx.x;
    const int w = tid >> 5, lane = tid & 31;
    const int g = lane >> 2, tg = lane & 3;
    const int mbase = (w >> 2) * 32;
    const int hbase = (w & 3) * 32;
    const int hw = w & 3;

    float acc[2][4][4];
#pragma unroll
    for (int mf = 0; mf < 2; mf++)
#pragma unroll
        for (int nf = 0; nf < 4; nf++)
#pragma unroll
            for (int t = 0; t < 4; t++) acc[mf][nf][t] = 0.f;

    for (int f0 = 0; f0 < F_; f0 += 32) {
#pragma unroll
        for (int it = 0; it < 2; it++) {            // sA: 64x32
            int idx = tid + it * 256;
            int mi = idx >> 3, k4 = idx & 7;
            float4 v = *(const float4*)&x[(m0 + mi) * F_ + f0 + k4 * 4];
            uint4 u = { f2tf(v.x), f2tf(v.y), f2tf(v.z), f2tf(v.w) };
            *(uint4*)&sA[mi][k4 * 4] = u;
        }
#pragma unroll
        for (int it = 0; it < 4; it++) {            // sB: 128x32
            int idx = tid + it * 256;
            int hh = idx >> 3, k4 = idx & 7;
            float4 v = *(const float4*)&W[hh * F_ + f0 + k4 * 4];
            uint4 u = { f2tf(v.x), f2tf(v.y), f2tf(v.z), f2tf(v.w) };
            *(uint4*)&sB[hh][k4 * 4] = u;
        }
        __syncthreads();
#pragma unroll
        for (int ks = 0; ks < 4; ks++) {
            int kb = ks * 8;
            unsigned afr[2][4], bfr[4][2];
#pragma unroll
            for (int mf = 0; mf < 2; mf++) {
                int mr = mbase + mf * 16 + g;
                afr[mf][0] = sA[mr    ][kb + tg];
                afr[mf][1] = sA[mr + 8][kb + tg];
                afr[mf][2] = sA[mr    ][kb + 4 + tg];
                afr[mf][3] = sA[mr + 8][kb + 4 + tg];
            }
#pragma unroll
            for (int nf = 0; nf < 4; nf++) {
                int cc = hbase + nf * 8 + g;
                bfr[nf][0] = sB[cc][kb + tg];
                bfr[nf][1] = sB[cc][kb + 4 + tg];
            }
#pragma unroll
            for (int mf = 0; mf < 2; mf++)
#pragma unroll
                for (int nf = 0; nf < 4; nf++)
                    mma8(acc[mf][nf], afr[mf], bfr[nf]);
        }
        __syncthreads();
    }

    float ps[4] = {0.f, 0.f, 0.f, 0.f};
    float pd[4] = {0.f, 0.f, 0.f, 0.f};
#pragma unroll
    for (int mf = 0; mf < 2; mf++) {
#pragma unroll
        for (int nf = 0; nf < 4; nf++) {
            int c = hbase + nf * 8 + 2 * tg;
            int r0 = m0 + mbase + mf * 16 + g;
            int r1 = r0 + 8;
            float v0 = acc[mf][nf][0], v1 = acc[mf][nf][1];
            float v2 = acc[mf][nf][2], v3 = acc[mf][nf][3];
            g_hTt[(long long)c       * ROWS + r0] = f2tf(v0);
            g_hTt[(long long)(c + 1) * ROWS + r0] = f2tf(v1);
            g_hTt[(long long)c       * ROWS + r1] = f2tf(v2);
            g_hTt[(long long)(c + 1) * ROWS + r1] = f2tf(v3);
            float as0 = a_src[c], as1 = a_src[c + 1];
            float ad0 = a_dst[c], ad1 = a_dst[c + 1];
            ps[mf * 2 + 0] += v0 * as0 + v1 * as1;
            ps[mf * 2 + 1] += v2 * as0 + v3 * as1;
            pd[mf * 2 + 0] += v0 * ad0 + v1 * ad1;
            pd[mf * 2 + 1] += v2 * ad0 + v3 * ad1;
        }
    }
#pragma unroll
    for (int off = 1; off <= 2; off <<= 1) {
#pragma unroll
        for (int s = 0; s < 4; s++) {
            ps[s] += __shfl_xor_sync(0xffffffffu, ps[s], off);
            pd[s] += __shfl_xor_sync(0xffffffffu, pd[s], off);
        }
    }
    if (tg == 0) {
#pragma unroll
        for (int s = 0; s < 4; s++) {
            int row = mbase + (s >> 1) * 16 + g + (s & 1) * 8;
            eps[hw][row] = ps[s];
            epd[hw][row] = pd[s];
        }
    }
    __syncthreads();
    if (tid < 64) {
        float s = eps[0][tid] + eps[1][tid] + eps[2][tid] + eps[3][tid];
        float d = epd[0][tid] + epd[1][tid] + epd[2][tid] + epd[3][tid];
        g_es[m0 + tid] = s;
        g_ed[m0 + tid] = d;
    }
}

// ---------------------------------------------------------------------------
// K2: softmax row stats. Mask bits cached in a u64 register (low regs),
// edb reloaded in pass 2 (L1-hot). Mask smem shared across batches.
// ---------------------------------------------------------------------------
__global__ __launch_bounds__(256) void k2_stats(const float* __restrict__ adjA)
{
    __shared__ unsigned char msk[N_];
    const int m = blockIdx.x;
    const int tid = threadIdx.x;
    const int warp = tid >> 5, lane = tid & 31;
#pragma unroll
    for (int it = 0; it < 8; it++) {
        int n = tid + it * 256;
        float adj = adjA[(long long)m * N_ + n] + (n == m ? 1.f : 0.f);
        msk[n] = (adj <= 0.f) ? 1 : 0;
    }
    __syncthreads();

    const int b = warp;
    const int r = b * N_ + m;
    const float es = g_es[r];
    const float* edb = g_ed + b * N_;

    unsigned long long bm = 0ull;
    float mx = -INFINITY;
#pragma unroll 8
    for (int t = 0; t < 64; t++) {
        int n = lane + 32 * t;
        float v = es + edb[n];
        float lr = fmaxf(v, 0.2f * v);
        unsigned long long k = msk[n];
        bm |= k << t;
        float s = k ? NEG_INF : lr;
        mx = fmaxf(mx, s);
    }
#pragma unroll
    for (int off = 16; off >= 1; off >>= 1)
        mx = fmaxf(mx, __shfl_xor_sync(0xffffffffu, mx, off));

    float sm = 0.f;
#pragma unroll 8
    for (int t = 0; t < 64; t++) {
        int n = lane + 32 * t;
        float v = es + edb[n];
        float lr = fmaxf(v, 0.2f * v);
        float s = ((bm >> t) & 1ull) ? NEG_INF : lr;
        sm += __expf(s - mx);
    }
#pragma unroll
    for (int off = 16; off >= 1; off >>= 1)
        sm += __shfl_xor_sync(0xffffffffu, sm, off);

    if (lane == 0) { g_mx[r] = mx; g_rs[r] = 1.f / sm; }
}

// ---------------------------------------------------------------------------
// K3: hp = elu(attn @ h), then FUSED fc2: x_proj = hp @ fc2w^T + fc2b.
// Mainloop: tf32 mma + ldmatrix + 3-stage cp.async ring, 1 sync/iter.
// Epilogue GEMM reuses the dynamic smem (sHP/sFW [64][132] tf32 tiles).
// Writes x_proj and g_xpwTt; g_hp eliminated.
// ---------------------------------------------------------------------------
constexpr int K3_WWORDS = 64 * 36;            // 2304
constexpr int K3_BWORDS = 128 * 36;           // 4608
constexpr int K3_SMEM   = (2 * K3_WWORDS + 3 * K3_BWORDS + 3 * 64) * 4;  // 74496 B

__global__ __launch_bounds__(256) void k3_attn(const float* __restrict__ adjA,
                                               const float* __restrict__ fc2w,
                                               const float* __restrict__ fc2b,
                                               const float* __restrict__ Wa,
                                               float* __restrict__ out)
{
    extern __shared__ unsigned dyn3[];
    unsigned* w_s = dyn3;                       // 2 bufs
    unsigned* sBp = dyn3 + 2 * K3_WWORDS;       // 3 stages
    float* s_mx = (float*)(dyn3 + 2 * K3_WWORDS + 3 * K3_BWORDS);
    float* s_rs = s_mx + 64;
    float* s_es = s_rs + 64;

    const int b  = blockIdx.x >> 5;
    const int m0 = (blockIdx.x & 31) * 64;
    const int rbase = b * N_ + m0;
    const int tid = threadIdx.x;
    const int w = tid >> 5, lane = tid & 31;
    const int g = lane >> 2, tg = lane & 3;
    const int mbase = (w >> 2) * 32;
    const int hbase = (w & 3) * 32;
    const long long bN = (long long)b * N_;

    if (tid < 64) {
        s_mx[tid] = g_mx[rbase + tid];
        s_rs[tid] = g_rs[rbase + tid];
        s_es[tid] = g_es[rbase + tid];
    }

    unsigned aBase[2], bBase[2];
#pragma unroll
    for (int mf = 0; mf < 2; mf++)
        aBase[mf] = smem_u32(w_s + (mbase + mf * 16 + (lane & 15)) * 36 + 4 * (lane >> 4));
#pragma unroll
    for (int p = 0; p < 2; p++)
        bBase[p] = smem_u32(sBp + (hbase + (2 * p + (lane >> 4)) * 8 + (lane & 7)) * 36
                                + 4 * ((lane >> 3) & 1));

    // prefetch tile 0 into stage 0
    {
#pragma unroll
        for (int it = 0; it < 4; it++) {
            int idx = tid + it * 256;
            int c = idx >> 3, kk4 = idx & 7;
            cp16(smem_u32(sBp + c * 36 + kk4 * 4),
                 &g_hTt[(long long)c * ROWS + bN + kk4 * 4]);
        }
        CP_COMMIT();
    }
    __syncthreads();

    float acc[2][4][4];
#pragma unroll
    for (int mf = 0; mf < 2; mf++)
#pragma unroll
        for (int nf = 0; nf < 4; nf++)
#pragma unroll
            for (int t = 0; t < 4; t++) acc[mf][nf][t] = 0.f;

    const int mi = tid >> 2;
    const int nb = (tid & 3) * 8;
    const int gm = m0 + mi;
    const float* arow = adjA + (long long)gm * N_;
    const float* edb  = g_ed + bN;
    const float es = s_es[mi], mxv = s_mx[mi], rs = s_rs[mi];

    for (int it = 0; it < 64; it++) {
        const int n0 = it * 32;
        const int wbuf = (it & 1) * K3_WWORDS;
        {
            float4 a4[2], e4[2];
            a4[0] = *(const float4*)(arow + n0 + nb);
            a4[1] = *(const float4*)(arow + n0 + nb + 4);
            e4[0] = *(const float4*)(edb  + n0 + nb);
            e4[1] = *(const float4*)(edb  + n0 + nb + 4);
            const float* ap = (const float*)a4;
            const float* ep = (const float*)e4;
#pragma unroll
            for (int jj = 0; jj < 8; jj++) {
                int n = n0 + nb + jj;
                float adj = ap[jj] + (n == gm ? 1.f : 0.f);
                float t = es + ep[jj];
                float lr = fmaxf(t, 0.2f * t);
                float sc = (adj <= 0.f) ? NEG_INF : lr;
                w_s[wbuf + mi * 36 + nb + jj] = f2tf(__expf(sc - mxv) * rs);
            }
        }
        if (it + 1 < 64) {
            const int st = ((it + 1) % 3) * K3_BWORDS;
            const long long gbase = bN + (long long)(it + 1) * 32;
#pragma unroll
            for (int c4 = 0; c4 < 4; c4++) {
                int idx = tid + c4 * 256;
                int c = idx >> 3, kk4 = idx & 7;
                cp16(smem_u32(sBp + st + c * 36 + kk4 * 4),
                     &g_hTt[(long long)c * ROWS + gbase + kk4 * 4]);
            }
        }
        CP_COMMIT();
        CP_WAIT1();
        __syncthreads();

        const unsigned aOff = (unsigned)(it & 1) * (K3_WWORDS * 4);
        const unsigned bOff = (unsigned)(it % 3) * (K3_BWORDS * 4);
#pragma unroll
        for (int ks = 0; ks < 4; ks++) {
            unsigned afr[2][4], bfr[4][2];
            ldm_x4(afr[0][0], afr[0][1], afr[0][2], afr[0][3], aBase[0] + aOff + ks * 32);
            ldm_x4(afr[1][0], afr[1][1], afr[1][2], afr[1][3], aBase[1] + aOff + ks * 32);
            ldm_x4(bfr[0][0], bfr[0][1], bfr[1][0], bfr[1][1], bBase[0] + bOff + ks * 32);
            ldm_x4(bfr[2][0], bfr[2][1], bfr[3][0], bfr[3][1], bBase[1] + bOff + ks * 32);
#pragma unroll
            for (int mf = 0; mf < 2; mf++)
#pragma unroll
                for (int nf = 0; nf < 4; nf++)
                    mma8(acc[mf][nf], afr[mf], bfr[nf]);
        }
    }

    // ---- fused fc2 GEMM (was k4) ----
    __syncthreads();                 // mainloop smem dead; cp.async drained
    unsigned* sHP = dyn3;            // [64][132] tf32(elu(hp))
    unsigned* sFW = dyn3 + 64 * 132; // [64][132] tf32(fc2w)

    // elu + store hp tile to smem
#pragma unroll
    for (int mf = 0; mf < 2; mf++) {
#pragma unroll
        for (int nf = 0; nf < 4; nf++) {
            int c = hbase + nf * 8 + 2 * tg;
            int r0l = mbase + mf * 16 + g;
            int r1l = r0l + 8;
            float v0 = acc[mf][nf][0], v1 = acc[mf][nf][1];
            float v2 = acc[mf][nf][2], v3 = acc[mf][nf][3];
            v0 = v0 > 0.f ? v0 : expm1f(v0);
            v1 = v1 > 0.f ? v1 : expm1f(v1);
            v2 = v2 > 0.f ? v2 : expm1f(v2);
            v3 = v3 > 0.f ? v3 : expm1f(v3);
            sHP[r0l * 132 + c]     = f2tf(v0);
            sHP[r0l * 132 + c + 1] = f2tf(v1);
            sHP[r1l * 132 + c]     = f2tf(v2);
            sHP[r1l * 132 + c + 1] = f2tf(v3);
        }
    }
    // load fc2w [64][128] -> sFW (tf32)
#pragma unroll
    for (int it = 0; it < 8; it++) {
        int idx = tid + it * 256;                  // 2048 float4
        int o = idx >> 5, k4 = idx & 31;
        float4 v = *(const float4*)&fc2w[o * H_ + k4 * 4];
        uint4 u = { f2tf(v.x), f2tf(v.y), f2tf(v.z), f2tf(v.w) };
        *(uint4*)&sFW[o * 132 + k4 * 4] = u;
    }
    __syncthreads();

    // epilogue GEMM: 64m x 64o, warps 2m x 4o (warp 32m x 16o)
    const int mbase2 = (w >> 2) * 32;
    const int obase2 = (w & 3) * 16;
    unsigned aB2[2];
#pragma unroll
    for (int mf = 0; mf < 2; mf++)
        aB2[mf] = smem_u32(sHP + (mbase2 + mf * 16 + (lane & 15)) * 132 + 4 * (lane >> 4));
    unsigned bB2 = smem_u32(sFW + (obase2 + (lane >> 4) * 8 + (lane & 7)) * 132
                                + 4 * ((lane >> 3) & 1));

    float acc2[2][2][4];
#pragma unroll
    for (int mf = 0; mf < 2; mf++)
#pragma unroll
        for (int nf = 0; nf < 2; nf++)
#pragma unroll
            for (int t = 0; t < 4; t++) acc2[mf][nf][t] = 0.f;

#pragma unroll
    for (int ks = 0; ks < 16; ks++) {
        unsigned afr[2][4], bfr[2][2];
        ldm_x4(afr[0][0], afr[0][1], afr[0][2], afr[0][3], aB2[0] + ks * 32);
        ldm_x4(afr[1][0], afr[1][1], afr[1][2], afr[1][3], aB2[1] + ks * 32);
        ldm_x4(bfr[0][0], bfr[0][1], bfr[1][0], bfr[1][1], bB2 + ks * 32);
#pragma unroll
        for (int mf = 0; mf < 2; mf++)
#pragma unroll
            for (int nf = 0; nf < 2; nf++)
                mma8(acc2[mf][nf], afr[mf], bfr[nf]);
    }

#pragma unroll
    for (int mf = 0; mf < 2; mf++) {
#pragma unroll
        for (int nf = 0; nf < 2; nf++) {
            int c = obase2 + nf * 8 + 2 * tg;
            int r0 = rbase + mbase2 + mf * 16 + g;
            int r1 = r0 + 8;
            float b0 = fc2b[c], b1 = fc2b[c + 1];
            float w0 = Wa[c],   w1 = Wa[c + 1];
            float v0 = acc2[mf][nf][0] + b0, v1 = acc2[mf][nf][1] + b1;
            float v2 = acc2[mf][nf][2] + b0, v3 = acc2[mf][nf][3] + b1;
            *(float2*)&out[OFF_XPROJ + (long long)r0 * O_ + c] = make_float2(v0, v1);
            *(float2*)&out[OFF_XPROJ + (long long)r1 * O_ + c] = make_float2(v2, v3);
            g_xpwTt[(long long)c       * ROWS + r0] = f2tf(v0 + w0);
            g_xpwTt[(long long)(c + 1) * ROWS + r0] = f2tf(v1 + w1);
            g_xpwTt[(long long)c       * ROWS + r1] = f2tf(v2 + w0);
            g_xpwTt[(long long)(c + 1) * ROWS + r1] = f2tf(v3 + w1);
        }
    }
}

// ---------------------------------------------------------------------------
// K5: logits = x_proj - A1^T @ xpw -- tf32 mma + ldmatrix + cp.async.
// dynamic smem: sA[3][128][36] | sB[3][64][36]. 1 sync/iter.
// ---------------------------------------------------------------------------
constexpr int K5_AWORDS = 128 * 36;           // 4608
constexpr int K5_BWORDS = 64 * 36;            // 2304
constexpr int K5_SMEM   = (3 * K5_AWORDS + 3 * K5_BWORDS) * 4;   // 82944 B

__global__ __launch_bounds__(256) void k5_logits(float* __restrict__ out)
{
    extern __shared__ unsigned dyn5[];
    unsigned* sAp = dyn5;
    unsigned* sBp = dyn5 + 3 * K5_AWORDS;

    const int b  = blockIdx.x >> 4;
    const int m0 = (blockIdx.x & 15) * 128;
    const int tid = threadIdx.x;
    const int w = tid >> 5, lane = tid & 31;
    const int g = lane >> 2, tg = lane & 3;
    const int mbase = (w >> 1) * 32;
    const int obase = (w & 1) * 32;
    const long long bN = (long long)b * N_;

    unsigned aBase[2], bBase[2];
#pragma unroll
    for (int mf = 0; mf < 2; mf++)
        aBase[mf] = smem_u32(sAp + (mbase + mf * 16 + (lane & 15)) * 36 + 4 * (lane >> 4));
#pragma unroll
    for (int p = 0; p < 2; p++)
        bBase[p] = smem_u32(sBp + (obase + (2 * p + (lane >> 4)) * 8 + (lane & 7)) * 36
                                + 4 * ((lane >> 3) & 1));

    // prefetch tile 0
    {
#pragma unroll
        for (int c4 = 0; c4 < 4; c4++) {
            int idx = tid + c4 * 256;
            int m = idx >> 3, kk4 = idx & 7;
            cp16(smem_u32(sAp + m * 36 + kk4 * 4),
                 &g_A1T[(long long)(m0 + m) * N_ + kk4 * 4]);
        }
#pragma unroll
        for (int c4 = 0; c4 < 2; c4++) {
            int idx = tid + c4 * 256;
            int o = idx >> 3, kk4 = idx & 7;
            cp16(smem_u32(sBp + o * 36 + kk4 * 4),
                 &g_xpwTt[(long long)o * ROWS + bN + kk4 * 4]);
        }
        CP_COMMIT();
    }

    float acc[2][4][4];
#pragma unroll
    for (int mf = 0; mf < 2; mf++)
#pragma unroll
        for (int nf = 0; nf < 4; nf++)
#pragma unroll
            for (int t = 0; t < 4; t++) acc[mf][nf][t] = 0.f;

    for (int it = 0; it < 64; it++) {
        if (it + 1 < 64) {
            const int stA = ((it + 1) % 3) * K5_AWORDS;
            const int stB = ((it + 1) % 3) * K5_BWORDS;
            const int n1 = (it + 1) * 32;
#pragma unroll
            for (int c4 = 0; c4 < 4; c4++) {
                int idx = tid + c4 * 256;
                int m = idx >> 3, kk4 = idx & 7;
                cp16(smem_u32(sAp + stA + m * 36 + kk4 * 4),
                     &g_A1T[(long long)(m0 + m) * N_ + n1 + kk4 * 4]);
            }
#pragma unroll
            for (int c4 = 0; c4 < 2; c4++) {
                int idx = tid + c4 * 256;
                int o = idx >> 3, kk4 = idx & 7;
                cp16(smem_u32(sBp + stB + o * 36 + kk4 * 4),
                     &g_xpwTt[(long long)o * ROWS + bN + n1 + kk4 * 4]);
            }
        }
        CP_COMMIT();
        CP_WAIT1();
        __syncthreads();

        const unsigned aOff = (unsigned)(it % 3) * (K5_AWORDS * 4);
        const unsigned bOff = (unsigned)(it % 3) * (K5_BWORDS * 4);
#pragma unroll
        for (int ks = 0; ks < 4; ks++) {
            unsigned afr[2][4], bfr[4][2];
            ldm_x4(afr[0][0], afr[0][1], afr[0][2], afr[0][3], aBase[0] + aOff + ks * 32);
            ldm_x4(afr[1][0], afr[1][1], afr[1][2], afr[1][3], aBase[1] + aOff + ks * 32);
            ldm_x4(bfr[0][0], bfr[0][1], bfr[1][0], bfr[1][1], bBase[0] + bOff + ks * 32);
            ldm_x4(bfr[2][0], bfr[2][1], bfr[3][0], bfr[3][1], bBase[1] + bOff + ks * 32);
#pragma unroll
            for (int mf = 0; mf < 2; mf++)
#pragma unroll
                for (int nf = 0; nf < 4; nf++)
                    mma8(acc[mf][nf], afr[mf], bfr[nf]);
        }
    }

#pragma unroll
    for (int mf = 0; mf < 2; mf++) {
#pragma unroll
        for (int nf = 0; nf < 4; nf++) {
            int c = obase + nf * 8 + 2 * tg;
            int r0 = b * N_ + m0 + mbase + mf * 16 + g;
            int r1 = r0 + 8;
            float2 xp0 = *(const float2*)&out[OFF_XPROJ + (long long)r0 * O_ + c];
            float2 xp1 = *(const float2*)&out[OFF_XPROJ + (long long)r1 * O_ + c];
            float2 o0, o1;
            o0.x = xp0.x - acc[mf][nf][0]; o0.y = xp0.y - acc[mf][nf][1];
            o1.x = xp1.x - acc[mf][nf][2]; o1.y = xp1.y - acc[mf][nf][3];
            *(float2*)&out[OFF_LOGITS + (long long)r0 * O_ + c] = o0;
            *(float2*)&out[OFF_LOGITS + (long long)r1 * O_ + c] = o1;
        }
    }
}

// ---------------------------------------------------------------------------
extern "C" void kernel_launch(void* const* d_in, const int* in_sizes, int n_in,
                              void* d_out, int out_size)
{
    const float* x     = (const float*)d_in[0];
    const float* adjA  = (const float*)d_in[1];
    const float* W     = (const float*)d_in[2];
    const float* a_src = (const float*)d_in[3];
    const float* a_dst = (const float*)d_in[4];
    const float* fc2w  = (const float*)d_in[5];
    const float* fc2b  = (const float*)d_in[6];
    const float* Wa    = (const float*)d_in[7];
    const float* z     = (const float*)d_in[8];
    const float* zpos  = (const float*)d_in[9];
    float* out = (float*)d_out;

    cudaFuncSetAttribute(k3_attn,   cudaFuncAttributeMaxDynamicSharedMemorySize, K3_SMEM);
    cudaFuncSetAttribute(k5_logits, cudaFuncAttributeMaxDynamicSharedMemorySize, K5_SMEM);

    k0_misc      <<<(N_ * N_ / 4 + 255) / 256, 256>>>(adjA, zpos, Wa, z, out);
    k0b_transpose<<<64 * 64, 256>>>(out);
    k1_h         <<<ROWS / 64, 256>>>(x, W, a_src, a_dst);
    k2_stats     <<<N_, 256>>>(adjA);
    k3_attn      <<<B_ * (N_ / 64), 256, K3_SMEM>>>(adjA, fc2w, fc2b, Wa, out);
    k5_logits    <<<B_ * (N_ / 128), 256, K5_SMEM>>>(out);
}

// round 14
// speedup vs baseline: 3.3153x; 1.1012x over previous
#include <cuda_runtime.h>
#include <math.h>

// Problem constants
constexpr int B_ = 8, N_ = 2048, F_ = 128, H_ = 128, O_ = 64;
constexpr int ROWS = B_ * N_;            // 16384
constexpr float NEG_INF = -1.0e9f;

// Output layout (tuple flattened in order)
constexpr long long OFF_XPROJ  = 0;
constexpr long long OFF_LOGITS = OFF_XPROJ  + (long long)B_ * N_ * O_;
constexpr long long OFF_ADJ1   = OFF_LOGITS + (long long)B_ * N_ * O_;
constexpr long long OFF_EYE    = OFF_ADJ1   + (long long)N_ * N_;
constexpr long long OFF_Z      = OFF_EYE    + (long long)N_ * N_;
constexpr long long OFF_ZPOS   = OFF_Z      + 1;                    // odd -> 4B only
constexpr long long OFF_ADJA   = OFF_ZPOS   + (long long)N_ * N_;   // odd
constexpr long long OFF_WA     = OFF_ADJA   + (long long)N_ * N_;

// Scratch (device globals). *t arrays hold tf32 bit patterns.
__device__ unsigned g_hTt  [H_ * ROWS];   // tf32(h^T)       (B-operand k3)
__device__ unsigned g_A1T  [N_ * N_];     // tf32(adj_A1^T)  (A-operand k5)
__device__ unsigned g_xpwTt[O_ * ROWS];   // tf32((xp+Wa)^T) (B-operand k5)
__device__ float    g_es   [ROWS];
__device__ float    g_ed   [ROWS];
__device__ float    g_mx   [ROWS];
__device__ float    g_rs   [ROWS];

// ---- helpers --------------------------------------------------------------
__device__ __forceinline__ unsigned f2tf(float f) {
    unsigned u; asm("cvt.rna.tf32.f32 %0, %1;" : "=r"(u) : "f"(f)); return u;
}
__device__ __forceinline__ void mma8(float* d, const unsigned* a, const unsigned* b) {
    asm volatile("mma.sync.aligned.m16n8k8.row.col.f32.tf32.tf32.f32 "
        "{%0,%1,%2,%3},{%4,%5,%6,%7},{%8,%9},{%0,%1,%2,%3};"
        : "+f"(d[0]), "+f"(d[1]), "+f"(d[2]), "+f"(d[3])
        : "r"(a[0]), "r"(a[1]), "r"(a[2]), "r"(a[3]), "r"(b[0]), "r"(b[1]));
}
__device__ __forceinline__ unsigned smem_u32(const void* p) {
    return (unsigned)__cvta_generic_to_shared(p);
}
__device__ __forceinline__ void ldm_x4(unsigned& r0, unsigned& r1,
                                       unsigned& r2, unsigned& r3, unsigned addr) {
    asm volatile("ldmatrix.sync.aligned.m8n8.x4.shared.b16 {%0,%1,%2,%3}, [%4];"
        : "=r"(r0), "=r"(r1), "=r"(r2), "=r"(r3) : "r"(addr));
}
__device__ __forceinline__ void cp16(unsigned dst, const void* src) {
    asm volatile("cp.async.cg.shared.global [%0], [%1], 16;" :: "r"(dst), "l"(src));
}
#define CP_COMMIT() asm volatile("cp.async.commit_group;")
#define CP_WAIT1()  asm volatile("cp.async.wait_group 1;" ::: "memory")

// fast sinh via exp (rel err ~1e-6, fine vs 1e-3 gate)
__device__ __forceinline__ float fast_sinh(float t) {
    float et = __expf(t);
    return 0.5f * (et - __fdividef(1.f, et));
}

// ---------------------------------------------------------------------------
// K0: elementwise outputs. adj_A1/eye stores stay float4 at g=4*i4 (aligned);
// zpos/adjA copies re-phased to d0=4*i4+3 so the odd-offset regions get
// aligned STG.128; head(3)/tail(1) elements handled by edge threads.
// ---------------------------------------------------------------------------
__global__ void k0_misc(const float* __restrict__ adjA,
                        const float* __restrict__ zpos,
                        const float* __restrict__ Wa,
                        const float* __restrict__ z,
                        float* __restrict__ out)
{
    constexpr int NN = N_ * N_;
    int i4 = blockIdx.x * blockDim.x + threadIdx.x;
    if (i4 < (NN / 4)) {
        int g = i4 * 4;
        float4 a4 = ((const float4*)adjA)[i4];
        const float* ap = (const float*)&a4;

        float4 s4; float* sp = (float*)&s4;
#pragma unroll
        for (int l = 0; l < 4; l++) {
            float c = fminf(fmaxf(ap[l], -3.f), 3.f);
            float s = fast_sinh(3.f * c);
            sp[l] = fminf(fmaxf(s, -1000.f), 1000.f);
        }
        ((float4*)(out + OFF_ADJ1))[i4] = s4;

        int row = g >> 11, col = g & 2047;
        float4 e4; float* ep = (float*)&e4;
#pragma unroll
        for (int l = 0; l < 4; l++) ep[l] = (col + l == row) ? 1.f : 0.f;
        ((float4*)(out + OFF_EYE))[i4] = e4;

        // aligned copies: dst indices d0..d0+3, (OFF+d0)%4==0
        if (i4 < NN / 4 - 1) {
            int d0 = g + 3;
            float4 zc, ac;
            zc.x = zpos[d0];     zc.y = zpos[d0 + 1];
            zc.z = zpos[d0 + 2]; zc.w = zpos[d0 + 3];
            ac.x = adjA[d0];     ac.y = adjA[d0 + 1];
            ac.z = adjA[d0 + 2]; ac.w = adjA[d0 + 3];
            *(float4*)(out + OFF_ZPOS + d0) = zc;
            *(float4*)(out + OFF_ADJA + d0) = ac;
        } else {   // last thread: tail element d = NN-1
            out[OFF_ZPOS + NN - 1] = zpos[NN - 1];
            out[OFF_ADJA + NN - 1] = adjA[NN - 1];
        }
        if (i4 == 0) {          // head elements d = 0,1,2
#pragma unroll
            for (int d = 0; d < 3; d++) {
                out[OFF_ZPOS + d] = zpos[d];
                out[OFF_ADJA + d] = adjA[d];
            }
        }
    }
    if (blockIdx.x == 0) {
        if (threadIdx.x < O_)  out[OFF_WA + threadIdx.x] = Wa[threadIdx.x];
        if (threadIdx.x == O_) out[OFF_Z] = z[0];
    }
}

// ---------------------------------------------------------------------------
// K0b: g_A1T = tf32(adj_A1^T)  (32x32 smem tiles)
// ---------------------------------------------------------------------------
__global__ __launch_bounds__(256) void k0b_transpose(const float* __restrict__ out)
{
    __shared__ float t[32][33];
    const float* A1 = out + OFF_ADJ1;
    int bx = blockIdx.x;
    int c0 = (bx & 63) * 32;
    int r0 = (bx >> 6) * 32;
    int tid = threadIdx.x;
    int lr = tid >> 5, lc = tid & 31;
#pragma unroll
    for (int it = 0; it < 4; it++) {
        int row = lr + it * 8;
        t[row][lc] = A1[(long long)(r0 + row) * N_ + c0 + lc];
    }
    __syncthreads();
#pragma unroll
    for (int it = 0; it < 4; it++) {
        int row = lr + it * 8;
        g_A1T[(long long)(c0 + row) * N_ + r0 + lc] = f2tf(t[lc][row]);
    }
}

// ---------------------------------------------------------------------------
// K1: h = x @ W^T -- tf32 mma + fused e_src/e_dst reduction.
// ---------------------------------------------------------------------------
__global__ __launch_bounds__(256) void k1_h(const float* __restrict__ x,
                                            const float* __restrict__ W,
                                            const float* __restrict__ a_src,
                                            const float* __restrict__ a_dst)
{
    __shared__ unsigned sA[64][36];
    __shared__ unsigned sB[128][36];
    __shared__ float eps[4][64], epd[4][64];
    const int m0 = blockIdx.x * 64;
    const int tid = threadIdx.x;
    const int w = tid >> 5, lane = tid & 31;
    const int g = lane >> 2, tg = lane & 3;
    const int mbase = (w >> 2) * 32;
    const int hbase = (w & 3) * 32;
    const int hw = w & 3;

    float acc[2][4][4];
#pragma unroll
    for (int mf = 0; mf < 2; mf++)
#pragma unroll
        for (int nf = 0; nf < 4; nf++)
#pragma unroll
            for (int t = 0; t < 4; t++) acc[mf][nf][t] = 0.f;

    for (int f0 = 0; f0 < F_; f0 += 32) {
#pragma unroll
        for (int it = 0; it < 2; it++) {
            int idx = tid + it * 256;
            int mi = idx >> 3, k4 = idx & 7;
            float4 v = *(const float4*)&x[(m0 + mi) * F_ + f0 + k4 * 4];
            uint4 u = { f2tf(v.x), f2tf(v.y), f2tf(v.z), f2tf(v.w) };
            *(uint4*)&sA[mi][k4 * 4] = u;
        }
#pragma unroll
        for (int it = 0; it < 4; it++) {
            int idx = tid + it * 256;
            int hh = idx >> 3, k4 = idx & 7;
            float4 v = *(const float4*)&W[hh * F_ + f0 + k4 * 4];
            uint4 u = { f2tf(v.x), f2tf(v.y), f2tf(v.z), f2tf(v.w) };
            *(uint4*)&sB[hh][k4 * 4] = u;
        }
        __syncthreads();
#pragma unroll
        for (int ks = 0; ks < 4; ks++) {
            int kb = ks * 8;
            unsigned afr[2][4], bfr[4][2];
#pragma unroll
            for (int mf = 0; mf < 2; mf++) {
                int mr = mbase + mf * 16 + g;
                afr[mf][0] = sA[mr    ][kb + tg];
                afr[mf][1] = sA[mr + 8][kb + tg];
                afr[mf][2] = sA[mr    ][kb + 4 + tg];
                afr[mf][3] = sA[mr + 8][kb + 4 + tg];
            }
#pragma unroll
            for (int nf = 0; nf < 4; nf++) {
                int cc = hbase + nf * 8 + g;
                bfr[nf][0] = sB[cc][kb + tg];
                bfr[nf][1] = sB[cc][kb + 4 + tg];
            }
#pragma unroll
            for (int mf = 0; mf < 2; mf++)
#pragma unroll
                for (int nf = 0; nf < 4; nf++)
                    mma8(acc[mf][nf], afr[mf], bfr[nf]);
        }
        __syncthreads();
    }

    float ps[4] = {0.f, 0.f, 0.f, 0.f};
    float pd[4] = {0.f, 0.f, 0.f, 0.f};
#pragma unroll
    for (int mf = 0; mf < 2; mf++) {
#pragma unroll
        for (int nf = 0; nf < 4; nf++) {
            int c = hbase + nf * 8 + 2 * tg;
            int r0 = m0 + mbase + mf * 16 + g;
            int r1 = r0 + 8;
            float v0 = acc[mf][nf][0], v1 = acc[mf][nf][1];
            float v2 = acc[mf][nf][2], v3 = acc[mf][nf][3];
            g_hTt[(long long)c       * ROWS + r0] = f2tf(v0);
            g_hTt[(long long)(c + 1) * ROWS + r0] = f2tf(v1);
            g_hTt[(long long)c       * ROWS + r1] = f2tf(v2);
            g_hTt[(long long)(c + 1) * ROWS + r1] = f2tf(v3);
            float as0 = a_src[c], as1 = a_src[c + 1];
            float ad0 = a_dst[c], ad1 = a_dst[c + 1];
            ps[mf * 2 + 0] += v0 * as0 + v1 * as1;
            ps[mf * 2 + 1] += v2 * as0 + v3 * as1;
            pd[mf * 2 + 0] += v0 * ad0 + v1 * ad1;
            pd[mf * 2 + 1] += v2 * ad0 + v3 * ad1;
        }
    }
#pragma unroll
    for (int off = 1; off <= 2; off <<= 1) {
#pragma unroll
        for (int s = 0; s < 4; s++) {
            ps[s] += __shfl_xor_sync(0xffffffffu, ps[s], off);
            pd[s] += __shfl_xor_sync(0xffffffffu, pd[s], off);
        }
    }
    if (tg == 0) {
#pragma unroll
        for (int s = 0; s < 4; s++) {
            int row = mbase + (s >> 1) * 16 + g + (s & 1) * 8;
            eps[hw][row] = ps[s];
            epd[hw][row] = pd[s];
        }
    }
    __syncthreads();
    if (tid < 64) {
        float s = eps[0][tid] + eps[1][tid] + eps[2][tid] + eps[3][tid];
        float d = epd[0][tid] + epd[1][tid] + epd[2][tid] + epd[3][tid];
        g_es[m0 + tid] = s;
        g_ed[m0 + tid] = d;
    }
}

// ---------------------------------------------------------------------------
// K2: softmax row stats. Pass 1: masked max of RAW ed (lrelu monotone ->
// lrelu applied once after reduce, bitwise-identical) + masked count.
// Pass 2: per-element exp for unmasked only; masked handled as
// cnt*exp(NEG_INF-mx) (0 normally, reproduces all-masked uniform rows).
// ---------------------------------------------------------------------------
__global__ __launch_bounds__(256) void k2_stats(const float* __restrict__ adjA)
{
    __shared__ unsigned char msk[N_];
    const int m = blockIdx.x;
    const int tid = threadIdx.x;
    const int warp = tid >> 5, lane = tid & 31;
#pragma unroll
    for (int it = 0; it < 8; it++) {
        int n = tid + it * 256;
        float adj = adjA[(long long)m * N_ + n] + (n == m ? 1.f : 0.f);
        msk[n] = (adj <= 0.f) ? 1 : 0;
    }
    __syncthreads();

    const int b = warp;
    const int r = b * N_ + m;
    const float es = g_es[r];
    const float* edb = g_ed + b * N_;

    float mxe = -INFINITY;
    int cnt = 0;
#pragma unroll 8
    for (int t = 0; t < 64; t++) {
        int n = lane + 32 * t;
        float ed = edb[n];
        int k = msk[n];
        mxe = fmaxf(mxe, k ? -INFINITY : ed);
        cnt += k;
    }
#pragma unroll
    for (int off = 16; off >= 1; off >>= 1) {
        mxe = fmaxf(mxe, __shfl_xor_sync(0xffffffffu, mxe, off));
        cnt += __shfl_xor_sync(0xffffffffu, cnt, off);
    }
    float mx;
    if (mxe == -INFINITY) mx = NEG_INF;
    else { float v = es + mxe; mx = fmaxf(v, 0.2f * v); }

    float sm = 0.f;
#pragma unroll 8
    for (int t = 0; t < 64; t++) {
        int n = lane + 32 * t;
        float v = es + edb[n];
        float lr = fmaxf(v, 0.2f * v);
        float e = __expf(lr - mx);
        sm += msk[n] ? 0.f : e;
    }
#pragma unroll
    for (int off = 16; off >= 1; off >>= 1)
        sm += __shfl_xor_sync(0xffffffffu, sm, off);

    if (lane == 0) {
        sm += (float)cnt * __expf(NEG_INF - mx);
        g_mx[r] = mx;
        g_rs[r] = 1.f / sm;
    }
}

// ---------------------------------------------------------------------------
// K3: hp = elu(attn @ h), then FUSED fc2: x_proj = hp @ fc2w^T + fc2b.
// Mainloop: tf32 mma + ldmatrix + 3-stage cp.async ring, 1 sync/iter.
// ---------------------------------------------------------------------------
constexpr int K3_WWORDS = 64 * 36;            // 2304
constexpr int K3_BWORDS = 128 * 36;           // 4608
constexpr int K3_SMEM   = (2 * K3_WWORDS + 3 * K3_BWORDS + 3 * 64) * 4;  // 74496 B

__global__ __launch_bounds__(256) void k3_attn(const float* __restrict__ adjA,
                                               const float* __restrict__ fc2w,
                                               const float* __restrict__ fc2b,
                                               const float* __restrict__ Wa,
                                               float* __restrict__ out)
{
    extern __shared__ unsigned dyn3[];
    unsigned* w_s = dyn3;                       // 2 bufs
    unsigned* sBp = dyn3 + 2 * K3_WWORDS;       // 3 stages
    float* s_mx = (float*)(dyn3 + 2 * K3_WWORDS + 3 * K3_BWORDS);
    float* s_rs = s_mx + 64;
    float* s_es = s_rs + 64;

    const int b  = blockIdx.x >> 5;
    const int m0 = (blockIdx.x & 31) * 64;
    const int rbase = b * N_ + m0;
    const int tid = threadIdx.x;
    const int w = tid >> 5, lane = tid & 31;
    const int g = lane >> 2, tg = lane & 3;
    const int mbase = (w >> 2) * 32;
    const int hbase = (w & 3) * 32;
    const long long bN = (long long)b * N_;

    if (tid < 64) {
        s_mx[tid] = g_mx[rbase + tid];
        s_rs[tid] = g_rs[rbase + tid];
        s_es[tid] = g_es[rbase + tid];
    }

    unsigned aBase[2], bBase[2];
#pragma unroll
    for (int mf = 0; mf < 2; mf++)
        aBase[mf] = smem_u32(w_s + (mbase + mf * 16 + (lane & 15)) * 36 + 4 * (lane >> 4));
#pragma unroll
    for (int p = 0; p < 2; p++)
        bBase[p] = smem_u32(sBp + (hbase + (2 * p + (lane >> 4)) * 8 + (lane & 7)) * 36
                                + 4 * ((lane >> 3) & 1));

    // prefetch tile 0 into stage 0
    {
#pragma unroll
        for (int it = 0; it < 4; it++) {
            int idx = tid + it * 256;
            int c = idx >> 3, kk4 = idx & 7;
            cp16(smem_u32(sBp + c * 36 + kk4 * 4),
                 &g_hTt[(long long)c * ROWS + bN + kk4 * 4]);
        }
        CP_COMMIT();
    }
    __syncthreads();

    float acc[2][4][4];
#pragma unroll
    for (int mf = 0; mf < 2; mf++)
#pragma unroll
        for (int nf = 0; nf < 4; nf++)
#pragma unroll
            for (int t = 0; t < 4; t++) acc[mf][nf][t] = 0.f;

    const int mi = tid >> 2;
    const int nb = (tid & 3) * 8;
    const int gm = m0 + mi;
    const float* arow = adjA + (long long)gm * N_;
    const float* edb  = g_ed + bN;
    const float es = s_es[mi], mxv = s_mx[mi], rs = s_rs[mi];

    for (int it = 0; it < 64; it++) {
        const int n0 = it * 32;
        const int wbuf = (it & 1) * K3_WWORDS;
        {
            float4 a4[2], e4[2];
            a4[0] = *(const float4*)(arow + n0 + nb);
            a4[1] = *(const float4*)(arow + n0 + nb + 4);
            e4[0] = *(const float4*)(edb  + n0 + nb);
            e4[1] = *(const float4*)(edb  + n0 + nb + 4);
            const float* ap = (const float*)a4;
            const float* ep = (const float*)e4;
#pragma unroll
            for (int jj = 0; jj < 8; jj++) {
                int n = n0 + nb + jj;
                float adj = ap[jj] + (n == gm ? 1.f : 0.f);
                float t = es + ep[jj];
                float lr = fmaxf(t, 0.2f * t);
                float sc = (adj <= 0.f) ? NEG_INF : lr;
                w_s[wbuf + mi * 36 + nb + jj] = f2tf(__expf(sc - mxv) * rs);
            }
        }
        if (it + 1 < 64) {
            const int st = ((it + 1) % 3) * K3_BWORDS;
            const long long gbase = bN + (long long)(it + 1) * 32;
#pragma unroll
            for (int c4 = 0; c4 < 4; c4++) {
                int idx = tid + c4 * 256;
                int c = idx >> 3, kk4 = idx & 7;
                cp16(smem_u32(sBp + st + c * 36 + kk4 * 4),
                     &g_hTt[(long long)c * ROWS + gbase + kk4 * 4]);
            }
        }
        CP_COMMIT();
        CP_WAIT1();
        __syncthreads();

        const unsigned aOff = (unsigned)(it & 1) * (K3_WWORDS * 4);
        const unsigned bOff = (unsigned)(it % 3) * (K3_BWORDS * 4);
#pragma unroll
        for (int ks = 0; ks < 4; ks++) {
            unsigned afr[2][4], bfr[4][2];
            ldm_x4(afr[0][0], afr[0][1], afr[0][2], afr[0][3], aBase[0] + aOff + ks * 32);
            ldm_x4(afr[1][0], afr[1][1], afr[1][2], afr[1][3], aBase[1] + aOff + ks * 32);
            ldm_x4(bfr[0][0], bfr[0][1], bfr[1][0], bfr[1][1], bBase[0] + bOff + ks * 32);
            ldm_x4(bfr[2][0], bfr[2][1], bfr[3][0], bfr[3][1], bBase[1] + bOff + ks * 32);
#pragma unroll
            for (int mf = 0; mf < 2; mf++)
#pragma unroll
                for (int nf = 0; nf < 4; nf++)
                    mma8(acc[mf][nf], afr[mf], bfr[nf]);
        }
    }

    // ---- fused fc2 GEMM ----
    __syncthreads();
    unsigned* sHP = dyn3;            // [64][132] tf32(elu(hp))
    unsigned* sFW = dyn3 + 64 * 132; // [64][132] tf32(fc2w)

#pragma unroll
    for (int mf = 0; mf < 2; mf++) {
#pragma unroll
        for (int nf = 0; nf < 4; nf++) {
            int c = hbase + nf * 8 + 2 * tg;
            int r0l = mbase + mf * 16 + g;
            int r1l = r0l + 8;
            float v0 = acc[mf][nf][0], v1 = acc[mf][nf][1];
            float v2 = acc[mf][nf][2], v3 = acc[mf][nf][3];
            v0 = v0 > 0.f ? v0 : expm1f(v0);
            v1 = v1 > 0.f ? v1 : expm1f(v1);
            v2 = v2 > 0.f ? v2 : expm1f(v2);
            v3 = v3 > 0.f ? v3 : expm1f(v3);
            sHP[r0l * 132 + c]     = f2tf(v0);
            sHP[r0l * 132 + c + 1] = f2tf(v1);
            sHP[r1l * 132 + c]     = f2tf(v2);
            sHP[r1l * 132 + c + 1] = f2tf(v3);
        }
    }
#pragma unroll
    for (int it = 0; it < 8; it++) {
        int idx = tid + it * 256;
        int o = idx >> 5, k4 = idx & 31;
        float4 v = *(const float4*)&fc2w[o * H_ + k4 * 4];
        uint4 u = { f2tf(v.x), f2tf(v.y), f2tf(v.z), f2tf(v.w) };
        *(uint4*)&sFW[o * 132 + k4 * 4] = u;
    }
    __syncthreads();

    const int mbase2 = (w >> 2) * 32;
    const int obase2 = (w & 3) * 16;
    unsigned aB2[2];
#pragma unroll
    for (int mf = 0; mf < 2; mf++)
        aB2[mf] = smem_u32(sHP + (mbase2 + mf * 16 + (lane & 15)) * 132 + 4 * (lane >> 4));
    unsigned bB2 = smem_u32(sFW + (obase2 + (lane >> 4) * 8 + (lane & 7)) * 132
                                + 4 * ((lane >> 3) & 1));

    float acc2[2][2][4];
#pragma unroll
    for (int mf = 0; mf < 2; mf++)
#pragma unroll
        for (int nf = 0; nf < 2; nf++)
#pragma unroll
            for (int t = 0; t < 4; t++) acc2[mf][nf][t] = 0.f;

#pragma unroll
    for (int ks = 0; ks < 16; ks++) {
        unsigned afr[2][4], bfr[2][2];
        ldm_x4(afr[0][0], afr[0][1], afr[0][2], afr[0][3], aB2[0] + ks * 32);
        ldm_x4(afr[1][0], afr[1][1], afr[1][2], afr[1][3], aB2[1] + ks * 32);
        ldm_x4(bfr[0][0], bfr[0][1], bfr[1][0], bfr[1][1], bB2 + ks * 32);
#pragma unroll
        for (int mf = 0; mf < 2; mf++)
#pragma unroll
            for (int nf = 0; nf < 2; nf++)
                mma8(acc2[mf][nf], afr[mf], bfr[nf]);
    }

#pragma unroll
    for (int mf = 0; mf < 2; mf++) {
#pragma unroll
        for (int nf = 0; nf < 2; nf++) {
            int c = obase2 + nf * 8 + 2 * tg;
            int r0 = rbase + mbase2 + mf * 16 + g;
            int r1 = r0 + 8;
            float b0 = fc2b[c], b1 = fc2b[c + 1];
            float w0 = Wa[c],   w1 = Wa[c + 1];
            float v0 = acc2[mf][nf][0] + b0, v1 = acc2[mf][nf][1] + b1;
            float v2 = acc2[mf][nf][2] + b0, v3 = acc2[mf][nf][3] + b1;
            *(float2*)&out[OFF_XPROJ + (long long)r0 * O_ + c] = make_float2(v0, v1);
            *(float2*)&out[OFF_XPROJ + (long long)r1 * O_ + c] = make_float2(v2, v3);
            g_xpwTt[(long long)c       * ROWS + r0] = f2tf(v0 + w0);
            g_xpwTt[(long long)(c + 1) * ROWS + r0] = f2tf(v1 + w1);
            g_xpwTt[(long long)c       * ROWS + r1] = f2tf(v2 + w0);
            g_xpwTt[(long long)(c + 1) * ROWS + r1] = f2tf(v3 + w1);
        }
    }
}

// ---------------------------------------------------------------------------
// K5: logits = x_proj - A1^T @ xpw -- tf32 mma + ldmatrix + cp.async.
// ---------------------------------------------------------------------------
constexpr int K5_AWORDS = 128 * 36;           // 4608
constexpr int K5_BWORDS = 64 * 36;            // 2304
constexpr int K5_SMEM   = (3 * K5_AWORDS + 3 * K5_BWORDS) * 4;   // 82944 B

__global__ __launch_bounds__(256) void k5_logits(float* __restrict__ out)
{
    extern __shared__ unsigned dyn5[];
    unsigned* sAp = dyn5;
    unsigned* sBp = dyn5 + 3 * K5_AWORDS;

    const int b  = blockIdx.x >> 4;
    const int m0 = (blockIdx.x & 15) * 128;
    const int tid = threadIdx.x;
    const int w = tid >> 5, lane = tid & 31;
    const int g = lane >> 2, tg = lane & 3;
    const int mbase = (w >> 1) * 32;
    const int obase = (w & 1) * 32;
    const long long bN = (long long)b * N_;

    unsigned aBase[2], bBase[2];
#pragma unroll
    for (int mf = 0; mf < 2; mf++)
        aBase[mf] = smem_u32(sAp + (mbase + mf * 16 + (lane & 15)) * 36 + 4 * (lane >> 4));
#pragma unroll
    for (int p = 0; p < 2; p++)
        bBase[p] = smem_u32(sBp + (obase + (2 * p + (lane >> 4)) * 8 + (lane & 7)) * 36
                                + 4 * ((lane >> 3) & 1));

    // prefetch tile 0
    {
#pragma unroll
        for (int c4 = 0; c4 < 4; c4++) {
            int idx = tid + c4 * 256;
            int m = idx >> 3, kk4 = idx & 7;
            cp16(smem_u32(sAp + m * 36 + kk4 * 4),
                 &g_A1T[(long long)(m0 + m) * N_ + kk4 * 4]);
        }
#pragma unroll
        for (int c4 = 0; c4 < 2; c4++) {
            int idx = tid + c4 * 256;
            int o = idx >> 3, kk4 = idx & 7;
            cp16(smem_u32(sBp + o * 36 + kk4 * 4),
                 &g_xpwTt[(long long)o * ROWS + bN + kk4 * 4]);
        }
        CP_COMMIT();
    }

    float acc[2][4][4];
#pragma unroll
    for (int mf = 0; mf < 2; mf++)
#pragma unroll
        for (int nf = 0; nf < 4; nf++)
#pragma unroll
            for (int t = 0; t < 4; t++) acc[mf][nf][t] = 0.f;

    for (int it = 0; it < 64; it++) {
        if (it + 1 < 64) {
            const int stA = ((it + 1) % 3) * K5_AWORDS;
            const int stB = ((it + 1) % 3) * K5_BWORDS;
            const int n1 = (it + 1) * 32;
#pragma unroll
            for (int c4 = 0; c4 < 4; c4++) {
                int idx = tid + c4 * 256;
                int m = idx >> 3, kk4 = idx & 7;
                cp16(smem_u32(sAp + stA + m * 36 + kk4 * 4),
                     &g_A1T[(long long)(m0 + m) * N_ + n1 + kk4 * 4]);
            }
#pragma unroll
            for (int c4 = 0; c4 < 2; c4++) {
                int idx = tid + c4 * 256;
                int o = idx >> 3, kk4 = idx & 7;
                cp16(smem_u32(sBp + stB + o * 36 + kk4 * 4),
                     &g_xpwTt[(long long)o * ROWS + bN + n1 + kk4 * 4]);
            }
        }
        CP_COMMIT();
        CP_WAIT1();
        __syncthreads();

        const unsigned aOff = (unsigned)(it % 3) * (K5_AWORDS * 4);
        const unsigned bOff = (unsigned)(it % 3) * (K5_BWORDS * 4);
#pragma unroll
        for (int ks = 0; ks < 4; ks++) {
            unsigned afr[2][4], bfr[4][2];
            ldm_x4(afr[0][0], afr[0][1], afr[0][2], afr[0][3], aBase[0] + aOff + ks * 32);
            ldm_x4(afr[1][0], afr[1][1], afr[1][2], afr[1][3], aBase[1] + aOff + ks * 32);
            ldm_x4(bfr[0][0], bfr[0][1], bfr[1][0], bfr[1][1], bBase[0] + bOff + ks * 32);
            ldm_x4(bfr[2][0], bfr[2][1], bfr[3][0], bfr[3][1], bBase[1] + bOff + ks * 32);
#pragma unroll
            for (int mf = 0; mf < 2; mf++)
#pragma unroll
                for (int nf = 0; nf < 4; nf++)
                    mma8(acc[mf][nf], afr[mf], bfr[nf]);
        }
    }

#pragma unroll
    for (int mf = 0; mf < 2; mf++) {
#pragma unroll
        for (int nf = 0; nf < 4; nf++) {
            int c = obase + nf * 8 + 2 * tg;
            int r0 = b * N_ + m0 + mbase + mf * 16 + g;
            int r1 = r0 + 8;
            float2 xp0 = *(const float2*)&out[OFF_XPROJ + (long long)r0 * O_ + c];
            float2 xp1 = *(const float2*)&out[OFF_XPROJ + (long long)r1 * O_ + c];
            float2 o0, o1;
            o0.x = xp0.x - acc[mf][nf][0]; o0.y = xp0.y - acc[mf][nf][1];
            o1.x = xp1.x - acc[mf][nf][2]; o1.y = xp1.y - acc[mf][nf][3];
            *(float2*)&out[OFF_LOGITS + (long long)r0 * O_ + c] = o0;
            *(float2*)&out[OFF_LOGITS + (long long)r1 * O_ + c] = o1;
        }
    }
}

// ---------------------------------------------------------------------------
extern "C" void kernel_launch(void* const* d_in, const int* in_sizes, int n_in,
                              void* d_out, int out_size)
{
    const float* x     = (const float*)d_in[0];
    const float* adjA  = (const float*)d_in[1];
    const float* W     = (const float*)d_in[2];
    const float* a_src = (const float*)d_in[3];
    const float* a_dst = (const float*)d_in[4];
    const float* fc2w  = (const float*)d_in[5];
    const float* fc2b  = (const float*)d_in[6];
    const float* Wa    = (const float*)d_in[7];
    const float* z     = (const float*)d_in[8];
    const float* zpos  = (const float*)d_in[9];
    float* out = (float*)d_out;

    cudaFuncSetAttribute(k3_attn,   cudaFuncAttributeMaxDynamicSharedMemorySize, K3_SMEM);
    cudaFuncSetAttribute(k5_logits, cudaFuncAttributeMaxDynamicSharedMemorySize, K5_SMEM);

    k0_misc      <<<(N_ * N_ / 4 + 255) / 256, 256>>>(adjA, zpos, Wa, z, out);
    k0b_transpose<<<64 * 64, 256>>>(out);
    k1_h         <<<ROWS / 64, 256>>>(x, W, a_src, a_dst);
    k2_stats     <<<N_, 256>>>(adjA);
    k3_attn      <<<B_ * (N_ / 64), 256, K3_SMEM>>>(adjA, fc2w, fc2b, Wa, out);
    k5_logits    <<<B_ * (N_ / 128), 256, K5_SMEM>>>(out);
}